// round 10
// baseline (speedup 1.0000x reference)
#include <cuda_runtime.h>
#include <cuda_bf16.h>
#include <math.h>
#include <cstdint>

#define B_  2
#define S_  2048
#define D_  1024
#define H_  16
#define HD_ 64
#define M_  (B_*S_)

// ---------------- scratch (no allocs allowed) ----------------
__device__ float g_E[M_], g_R[M_];
__device__ __nv_bfloat16 g_xhi [M_*D_], g_xlo [M_*D_];
__device__ __nv_bfloat16 g_qhi [M_*D_], g_qlo [M_*D_];
__device__ __nv_bfloat16 g_khi [M_*D_], g_klo [M_*D_];
__device__ __nv_bfloat16 g_vhi [M_*D_], g_vlo [M_*D_];
__device__ __nv_bfloat16 g_aohi[M_*D_], g_aolo[M_*D_];
__device__ __nv_bfloat16 g_wthi[4u*D_*D_], g_wtlo[4u*D_*D_];

// ================= helpers =================
__device__ __forceinline__ uint32_t smem_u32(const void* p) {
    uint32_t a;
    asm("{ .reg .u64 t; cvta.to.shared.u64 t, %1; cvt.u32.u64 %0, t; }" : "=r"(a) : "l"(p));
    return a;
}
__device__ __forceinline__ void ldsm4(uint32_t* r, uint32_t a) {
    asm volatile("ldmatrix.sync.aligned.m8n8.x4.shared.b16 {%0,%1,%2,%3}, [%4];"
        : "=r"(r[0]), "=r"(r[1]), "=r"(r[2]), "=r"(r[3]) : "r"(a));
}
__device__ __forceinline__ void ldsm4t(uint32_t* r, uint32_t a) {
    asm volatile("ldmatrix.sync.aligned.m8n8.x4.trans.shared.b16 {%0,%1,%2,%3}, [%4];"
        : "=r"(r[0]), "=r"(r[1]), "=r"(r[2]), "=r"(r[3]) : "r"(a));
}
__device__ __forceinline__ void mma_bf16(float* c, const uint32_t* a, const uint32_t* b) {
    asm volatile("mma.sync.aligned.m16n8k16.row.col.f32.bf16.bf16.f32 "
        "{%0,%1,%2,%3}, {%4,%5,%6,%7}, {%8,%9}, {%0,%1,%2,%3};"
        : "+f"(c[0]), "+f"(c[1]), "+f"(c[2]), "+f"(c[3])
        : "r"(a[0]), "r"(a[1]), "r"(a[2]), "r"(a[3]), "r"(b[0]), "r"(b[1]));
}
__device__ __forceinline__ uint32_t pack2(float lo, float hi) {
    uint32_t r;
    asm("cvt.rn.bf16x2.f32 %0, %1, %2;" : "=r"(r) : "f"(hi), "f"(lo));
    return r;
}
__device__ __forceinline__ float bf16x2_lo(uint32_t v) { return __uint_as_float(v << 16); }
__device__ __forceinline__ float bf16x2_hi(uint32_t v) { return __uint_as_float(v & 0xffff0000u); }

#define CP16(dst, src) asm volatile("cp.async.cg.shared.global [%0], [%1], 16;" :: "r"(dst), "l"(src))
#define CP_COMMIT()    asm volatile("cp.async.commit_group;" ::: "memory")
#define CP_WAIT0()     asm volatile("cp.async.wait_group 0;" ::: "memory")

// FFMA-only exp (x <= 0 expected)
__device__ __forceinline__ float fast_exp(float x) {
    x = fmaxf(x, -80.0f);
    float t = x * 1.4426950408889634f;
    float z = t + 12582912.0f;
    int  ni = __float_as_int(z) - 0x4B400000;
    float n = z - 12582912.0f;
    float g = fmaf(n, -0.6931471805599453f, x);
    float p = 1.3888889e-3f;
    p = fmaf(p, g, 8.3333333e-3f);
    p = fmaf(p, g, 4.1666667e-2f);
    p = fmaf(p, g, 1.6666667e-1f);
    p = fmaf(p, g, 0.5f);
    p = fmaf(p, g, 1.0f);
    p = fmaf(p, g, 1.0f);
    return p * __int_as_float((ni + 127) << 23);
}

// ---------------- small prep kernels ----------------
__global__ void prep_kernel(const float* __restrict__ ts, const float* __restrict__ td) {
    int i = blockIdx.x * 256 + threadIdx.x;
    if (i < M_) {
        float e = expf(td[0] * ts[i]);
        g_E[i] = e;
        g_R[i] = 1.0f / e;
    }
}
__global__ __launch_bounds__(256) void split_kernel(const float* __restrict__ src,
                                                    __nv_bfloat16* __restrict__ hi,
                                                    __nv_bfloat16* __restrict__ lo) {
    int i = blockIdx.x * 256 + threadIdx.x;
    float f = src[i];
    __nv_bfloat16 h = __float2bfloat16_rn(f);
    hi[i] = h;
    lo[i] = __float2bfloat16_rn(f - __bfloat162float(h));
}
__global__ __launch_bounds__(256) void transpose_split_all(
    const float* __restrict__ W0, const float* __restrict__ W1,
    const float* __restrict__ W2, const float* __restrict__ W3,
    __nv_bfloat16* __restrict__ hi, __nv_bfloat16* __restrict__ lo)
{
    __shared__ float tile[32][33];
    int z = blockIdx.z;
    const float* W = (z == 0) ? W0 : (z == 1) ? W1 : (z == 2) ? W2 : W3;
    size_t zoff = (size_t)z * D_ * D_;
    int tx = threadIdx.x, ty = threadIdx.y;
    int n0 = blockIdx.x * 32, k0 = blockIdx.y * 32;
#pragma unroll
    for (int j = 0; j < 32; j += 8)
        tile[ty + j][tx] = W[(size_t)(k0 + ty + j) * D_ + n0 + tx];
    __syncthreads();
#pragma unroll
    for (int j = 0; j < 32; j += 8) {
        float f = tile[tx][ty + j];
        __nv_bfloat16 h = __float2bfloat16_rn(f);
        size_t o = zoff + (size_t)(n0 + ty + j) * D_ + k0 + tx;
        hi[o] = h;
        lo[o] = __float2bfloat16_rn(f - __bfloat162float(h));
    }
}

// ---------------- HMMA split-bf16 GEMM core (cp.async 2-stage) ----------------
static constexpr int G_STAGE = 40960;
static constexpr int G_SMEM  = 2 * G_STAGE;

__device__ __forceinline__ void gemm_issue_chunk(
    uint32_t sb, int stage,
    const __nv_bfloat16* Ahi, const __nv_bfloat16* Alo,
    const __nv_bfloat16* Bhi, const __nv_bfloat16* Blo,
    int m0, int n0, int k0, int tid)
{
    uint32_t st = sb + stage * G_STAGE;
#pragma unroll
    for (int j = 0; j < 8; j++) {
        int rem = tid + (j & 1) * 256;
        int r = rem >> 2, c4 = rem & 3;
        const __nv_bfloat16* base = (j < 2) ? Ahi : (j < 4) ? Alo : (j < 6) ? Bhi : Blo;
        int rowbase = (j < 4) ? m0 : n0;
        uint32_t dst = st + (uint32_t)(j >> 1) * 10240u + (uint32_t)(r * 80 + c4 * 16);
        const __nv_bfloat16* src = base + (size_t)(rowbase + r) * D_ + k0 + c4 * 8;
        CP16(dst, src);
    }
    CP_COMMIT();
}

template<int MODE>   // 0: fp32 out, 1: split-bf16 out
__device__ __forceinline__ void gemm_body(
    const __nv_bfloat16* Ahi, const __nv_bfloat16* Alo,
    const __nv_bfloat16* Bhi, const __nv_bfloat16* Blo,
    const float* bias, float scale,
    float* Cf, __nv_bfloat16* Chi, __nv_bfloat16* Clo, char* smem)
{
    uint32_t sb = smem_u32(smem);
    int tid = threadIdx.x, l = tid & 31, wid = tid >> 5;
    int wm = wid >> 2, wn = wid & 3;
    int m0 = blockIdx.y * 128, n0 = blockIdx.x * 128;

    float acc[4][4][4];
#pragma unroll
    for (int a = 0; a < 4; a++)
#pragma unroll
        for (int b2 = 0; b2 < 4; b2++)
#pragma unroll
            for (int c = 0; c < 4; c++) acc[a][b2][c] = 0.f;

    gemm_issue_chunk(sb, 0, Ahi, Alo, Bhi, Blo, m0, n0, 0, tid);

    for (int kc = 0; kc < 32; kc++) {
        CP_WAIT0();
        __syncthreads();
        if (kc + 1 < 32)
            gemm_issue_chunk(sb, (kc + 1) & 1, Ahi, Alo, Bhi, Blo, m0, n0, (kc + 1) * 32, tid);

        uint32_t st  = sb + (kc & 1) * G_STAGE;
        uint32_t bAh = st, bAl = st + 10240, bBh = st + 20480, bBl = st + 30720;
#pragma unroll
        for (int s = 0; s < 2; s++) {
            int k0 = s * 16;
            uint32_t ah[4][4], al[4][4], bh[2][4], bl[2][4];
#pragma unroll
            for (int mi = 0; mi < 4; mi++) {
                int row = wm * 64 + mi * 16 + (l & 15);
                int col = k0 + ((l >> 4) << 3);
                uint32_t off = (uint32_t)(row * 40 + col) * 2;
                ldsm4(ah[mi], bAh + off);
                ldsm4(al[mi], bAl + off);
            }
#pragma unroll
            for (int np = 0; np < 2; np++) {
                int row = wn * 32 + np * 16 + (l & 7) + ((l >> 4) << 3);
                int col = k0 + (((l >> 3) & 1) << 3);
                uint32_t off = (uint32_t)(row * 40 + col) * 2;
                ldsm4(bh[np], bBh + off);
                ldsm4(bl[np], bBl + off);
            }
            // stream-outermost: dependent MMAs on the same accumulator are 16 apart
#pragma unroll
            for (int mi = 0; mi < 4; mi++)
#pragma unroll
                for (int ni = 0; ni < 4; ni++)
                    mma_bf16(acc[mi][ni], ah[mi], &bh[ni >> 1][(ni & 1) * 2]);
#pragma unroll
            for (int mi = 0; mi < 4; mi++)
#pragma unroll
                for (int ni = 0; ni < 4; ni++)
                    mma_bf16(acc[mi][ni], ah[mi], &bl[ni >> 1][(ni & 1) * 2]);
#pragma unroll
            for (int mi = 0; mi < 4; mi++)
#pragma unroll
                for (int ni = 0; ni < 4; ni++)
                    mma_bf16(acc[mi][ni], al[mi], &bh[ni >> 1][(ni & 1) * 2]);
        }
    }
    // epilogue
#pragma unroll
    for (int mi = 0; mi < 4; mi++) {
        int row0 = m0 + wm * 64 + mi * 16 + (l >> 2);
#pragma unroll
        for (int ni = 0; ni < 4; ni++) {
            int col = n0 + wn * 32 + ni * 8 + ((l & 3) << 1);
            float b0 = bias[col], b1 = bias[col + 1];
            float v00 = (acc[mi][ni][0] + b0) * scale;
            float v01 = (acc[mi][ni][1] + b1) * scale;
            float v10 = (acc[mi][ni][2] + b0) * scale;
            float v11 = (acc[mi][ni][3] + b1) * scale;
            size_t o0 = (size_t)row0 * D_ + col;
            size_t o1 = o0 + (size_t)8 * D_;
            if (MODE == 0) {
                *(float2*)(Cf + o0) = make_float2(v00, v01);
                *(float2*)(Cf + o1) = make_float2(v10, v11);
            } else {
                __nv_bfloat162 h0, h1, l0p, l1p;
                h0.x = __float2bfloat16_rn(v00); h0.y = __float2bfloat16_rn(v01);
                h1.x = __float2bfloat16_rn(v10); h1.y = __float2bfloat16_rn(v11);
                l0p.x = __float2bfloat16_rn(v00 - __bfloat162float(h0.x));
                l0p.y = __float2bfloat16_rn(v01 - __bfloat162float(h0.y));
                l1p.x = __float2bfloat16_rn(v10 - __bfloat162float(h1.x));
                l1p.y = __float2bfloat16_rn(v11 - __bfloat162float(h1.y));
                *(__nv_bfloat162*)(Chi + o0) = h0;
                *(__nv_bfloat162*)(Chi + o1) = h1;
                *(__nv_bfloat162*)(Clo + o0) = l0p;
                *(__nv_bfloat162*)(Clo + o1) = l1p;
            }
        }
    }
}

__global__ __launch_bounds__(256) void gemm_qkv(
    const float* __restrict__ bq, const float* __restrict__ bk, const float* __restrict__ bv)
{
    extern __shared__ char smem[];
    int z = blockIdx.z;
    const size_t WSZ = (size_t)D_ * D_;
    const __nv_bfloat16* Bh = g_wthi + (size_t)z * WSZ;
    const __nv_bfloat16* Bl = g_wtlo + (size_t)z * WSZ;
    const float* bias = (z == 0) ? bq : (z == 1) ? bk : bv;
    __nv_bfloat16* Chi = (z == 0) ? g_qhi : (z == 1) ? g_khi : g_vhi;
    __nv_bfloat16* Clo = (z == 0) ? g_qlo : (z == 1) ? g_klo : g_vlo;
    float scale = (z == 0) ? 0.125f : 1.0f;
    gemm_body<1>(g_xhi, g_xlo, Bh, Bl, bias, scale, nullptr, Chi, Clo, smem);
}

__global__ __launch_bounds__(256) void gemm_o(const float* __restrict__ bo, float* __restrict__ out)
{
    extern __shared__ char smem[];
    const size_t WSZ = (size_t)D_ * D_;
    gemm_body<0>(g_aohi, g_aolo, g_wthi + 3 * WSZ, g_wtlo + 3 * WSZ, bo, 1.0f, out, nullptr, nullptr, smem);
}

// ---------------- HMMA flash attention (cp.async 2-stage) ----------------
static constexpr int A_STAGE = 37376;
static constexpr int A_SMEM  = 2 * A_STAGE;

__device__ __forceinline__ void attn_issue_tile(uint32_t sb, int stage, int b, int h, int kt, int tid) {
    uint32_t st = sb + stage * A_STAGE;
#pragma unroll
    for (int j = 0; j < 16; j++) {
        int a = j >> 2;
        int rem = tid + (j & 3) * 128;
        int r = rem >> 3, c = rem & 7;
        const __nv_bfloat16* base = (a == 0) ? g_khi : (a == 1) ? g_klo : (a == 2) ? g_vhi : g_vlo;
        uint32_t dst = st + (uint32_t)a * 9216u + (uint32_t)(r * 144 + c * 16);
        const __nv_bfloat16* src = base + (size_t)(b * S_ + kt + r) * D_ + h * HD_ + c * 8;
        CP16(dst, src);
    }
    if (tid < 16)      CP16(st + 36864u + tid * 16, &g_E[b * S_ + kt + tid * 4]);
    else if (tid < 32) CP16(st + 37120u + (tid - 16) * 16, &g_R[b * S_ + kt + (tid - 16) * 4]);
    CP_COMMIT();
}

__global__ __launch_bounds__(128) void attn_mma() {
    extern __shared__ char smem[];
    uint32_t sb = smem_u32(smem);
    int tid = threadIdx.x, l = tid & 31, wid = tid >> 5;
    int h = blockIdx.y, b = blockIdx.z;
    int q0 = blockIdx.x * 64;

    // ---- stage Q (hi then lo) through stage-0 region, pull frags ----
    __nv_bfloat16* qstage = (__nv_bfloat16*)smem;
    uint32_t bQ = sb;
    uint32_t qh[4][4], ql[4][4];
#pragma unroll
    for (int t = 0; t < 4; t++) {
        int i = tid + t * 128;
        int r = i >> 3, c8 = (i & 7) << 3;
        *(uint4*)(qstage + r * 72 + c8) =
            *(const uint4*)(g_qhi + (size_t)(b * S_ + q0 + r) * D_ + h * HD_ + c8);
    }
    __syncthreads();
#pragma unroll
    for (int ks = 0; ks < 4; ks++) {
        int row = wid * 16 + (l & 15);
        int col = ks * 16 + ((l >> 4) << 3);
        ldsm4(qh[ks], bQ + (uint32_t)(row * 72 + col) * 2);
    }
    __syncthreads();
#pragma unroll
    for (int t = 0; t < 4; t++) {
        int i = tid + t * 128;
        int r = i >> 3, c8 = (i & 7) << 3;
        *(uint4*)(qstage + r * 72 + c8) =
            *(const uint4*)(g_qlo + (size_t)(b * S_ + q0 + r) * D_ + h * HD_ + c8);
    }
    __syncthreads();
#pragma unroll
    for (int ks = 0; ks < 4; ks++) {
        int row = wid * 16 + (l & 15);
        int col = ks * 16 + ((l >> 4) << 3);
        ldsm4(ql[ks], bQ + (uint32_t)(row * 72 + col) * 2);
    }
    __syncthreads();

    int r0 = wid * 16 + (l >> 2), r1 = r0 + 8;
    float Ei0 = g_E[b * S_ + q0 + r0], Ri0 = g_R[b * S_ + q0 + r0];
    float Ei1 = g_E[b * S_ + q0 + r1], Ri1 = g_R[b * S_ + q0 + r1];

    float Oa[8][4];
#pragma unroll
    for (int f = 0; f < 8; f++)
#pragma unroll
        for (int c = 0; c < 4; c++) Oa[f][c] = 0.f;
    float m0v = -1e30f, m1v = -1e30f, l0v = 0.f, l1v = 0.f;

    attn_issue_tile(sb, 0, b, h, 0, tid);

    for (int t = 0; t < S_ / 64; t++) {
        CP_WAIT0();
        __syncthreads();
        if (t + 1 < S_ / 64)
            attn_issue_tile(sb, (t + 1) & 1, b, h, (t + 1) * 64, tid);

        uint32_t st  = sb + (t & 1) * A_STAGE;
        uint32_t bKh = st, bKl = st + 9216, bVh = st + 18432, bVl = st + 27648;
        const float* sE = (const float*)(smem + (t & 1) * A_STAGE + 36864);
        const float* sR = (const float*)(smem + (t & 1) * A_STAGE + 37120);

        // scores: S = qhi.Khi + qhi.Klo + qlo.Khi  (stream-outermost, deps 8 apart)
        float Sa[8][4];
#pragma unroll
        for (int f = 0; f < 8; f++)
#pragma unroll
            for (int c = 0; c < 4; c++) Sa[f][c] = 0.f;
#pragma unroll
        for (int ks = 0; ks < 4; ks++) {
            uint32_t kh[4][4], kl[4][4];
#pragma unroll
            for (int g2 = 0; g2 < 4; g2++) {
                int row = g2 * 16 + (l & 7) + ((l >> 4) << 3);
                int col = ks * 16 + (((l >> 3) & 1) << 3);
                uint32_t off = (uint32_t)(row * 72 + col) * 2;
                ldsm4(kh[g2], bKh + off);
                ldsm4(kl[g2], bKl + off);
            }
#pragma unroll
            for (int f = 0; f < 8; f++)
                mma_bf16(Sa[f], qh[ks], &kh[f >> 1][(f & 1) * 2]);
#pragma unroll
            for (int f = 0; f < 8; f++)
                mma_bf16(Sa[f], qh[ks], &kl[f >> 1][(f & 1) * 2]);
#pragma unroll
            for (int f = 0; f < 8; f++)
                mma_bf16(Sa[f], ql[ks], &kh[f >> 1][(f & 1) * 2]);
        }

        // decay + tile max
        int c0 = (l & 3) << 1;
        float mx0 = -1e30f, mx1 = -1e30f;
#pragma unroll
        for (int f = 0; f < 8; f++) {
            int j = f * 8 + c0;
            float Ej0 = sE[j], Rj0 = sR[j], Ej1 = sE[j + 1], Rj1 = sR[j + 1];
            Sa[f][0] *= fminf(Ei0 * Rj0, Ej0 * Ri0);
            Sa[f][1] *= fminf(Ei0 * Rj1, Ej1 * Ri0);
            Sa[f][2] *= fminf(Ei1 * Rj0, Ej0 * Ri1);
            Sa[f][3] *= fminf(Ei1 * Rj1, Ej1 * Ri1);
            mx0 = fmaxf(mx0, fmaxf(Sa[f][0], Sa[f][1]));
            mx1 = fmaxf(mx1, fmaxf(Sa[f][2], Sa[f][3]));
        }
        mx0 = fmaxf(mx0, __shfl_xor_sync(0xffffffffu, mx0, 1));
        mx0 = fmaxf(mx0, __shfl_xor_sync(0xffffffffu, mx0, 2));
        mx1 = fmaxf(mx1, __shfl_xor_sync(0xffffffffu, mx1, 1));
        mx1 = fmaxf(mx1, __shfl_xor_sync(0xffffffffu, mx1, 2));

        float mn0 = fmaxf(m0v, mx0), mn1 = fmaxf(m1v, mx1);
        float sc0 = fast_exp(m0v - mn0), sc1 = fast_exp(m1v - mn1);
        m0v = mn0; m1v = mn1;
        l0v *= sc0; l1v *= sc1;
#pragma unroll
        for (int f = 0; f < 8; f++) {
            Oa[f][0] *= sc0; Oa[f][1] *= sc0;
            Oa[f][2] *= sc1; Oa[f][3] *= sc1;
        }

        // p = exp(s - m), split into bf16 hi/lo A-frags
        uint32_t Ph[8][2], Pl[8][2];
        float rs0 = 0.f, rs1 = 0.f;
#pragma unroll
        for (int f = 0; f < 8; f++) {
            float p00 = fast_exp(Sa[f][0] - mn0);
            float p01 = fast_exp(Sa[f][1] - mn0);
            float p10 = fast_exp(Sa[f][2] - mn1);
            float p11 = fast_exp(Sa[f][3] - mn1);
            rs0 += p00 + p01; rs1 += p10 + p11;
            uint32_t h0 = pack2(p00, p01);
            uint32_t h1 = pack2(p10, p11);
            Ph[f][0] = h0; Ph[f][1] = h1;
            Pl[f][0] = pack2(p00 - bf16x2_lo(h0), p01 - bf16x2_hi(h0));
            Pl[f][1] = pack2(p10 - bf16x2_lo(h1), p11 - bf16x2_hi(h1));
        }
        rs0 += __shfl_xor_sync(0xffffffffu, rs0, 1);
        rs0 += __shfl_xor_sync(0xffffffffu, rs0, 2);
        rs1 += __shfl_xor_sync(0xffffffffu, rs1, 1);
        rs1 += __shfl_xor_sync(0xffffffffu, rs1, 2);
        l0v += rs0; l1v += rs1;

        // O += Phi.Vhi + Phi.Vlo + Plo.Vhi (V frags hoisted per ks; streams 8 apart)
#pragma unroll
        for (int ks = 0; ks < 4; ks++) {
            uint32_t pah[4] = {Ph[2*ks][0], Ph[2*ks][1], Ph[2*ks+1][0], Ph[2*ks+1][1]};
            uint32_t pal[4] = {Pl[2*ks][0], Pl[2*ks][1], Pl[2*ks+1][0], Pl[2*ks+1][1]};
            uint32_t vh[4][4], vl[4][4];
#pragma unroll
            for (int db = 0; db < 4; db++) {
                int row = ks * 16 + (l & 7) + (((l >> 3) & 1) << 3);
                int col = db * 16 + ((l >> 4) << 3);
                uint32_t off = (uint32_t)(row * 72 + col) * 2;
                ldsm4t(vh[db], bVh + off);
                ldsm4t(vl[db], bVl + off);
            }
#pragma unroll
            for (int db = 0; db < 4; db++) {
                mma_bf16(Oa[2*db],   pah, &vh[db][0]);
                mma_bf16(Oa[2*db+1], pah, &vh[db][2]);
            }
#pragma unroll
            for (int db = 0; db < 4; db++) {
                mma_bf16(Oa[2*db],   pah, &vl[db][0]);
                mma_bf16(Oa[2*db+1], pah, &vl[db][2]);
            }
#pragma unroll
            for (int db = 0; db < 4; db++) {
                mma_bf16(Oa[2*db],   pal, &vh[db][0]);
                mma_bf16(Oa[2*db+1], pal, &vh[db][2]);
            }
        }
    }

    // normalize + split-write ao
    float inv0 = 1.0f / l0v, inv1 = 1.0f / l1v;
    int c0 = (l & 3) << 1;
    size_t ro0 = (size_t)(b * S_ + q0 + r0) * D_ + h * HD_;
    size_t ro1 = (size_t)(b * S_ + q0 + r1) * D_ + h * HD_;
#pragma unroll
    for (int f = 0; f < 8; f++) {
        int d = f * 8 + c0;
        float v00 = Oa[f][0] * inv0, v01 = Oa[f][1] * inv0;
        float v10 = Oa[f][2] * inv1, v11 = Oa[f][3] * inv1;
        __nv_bfloat162 h0, h1, lo0, lo1;
        h0.x = __float2bfloat16_rn(v00); h0.y = __float2bfloat16_rn(v01);
        h1.x = __float2bfloat16_rn(v10); h1.y = __float2bfloat16_rn(v11);
        lo0.x = __float2bfloat16_rn(v00 - __bfloat162float(h0.x));
        lo0.y = __float2bfloat16_rn(v01 - __bfloat162float(h0.y));
        lo1.x = __float2bfloat16_rn(v10 - __bfloat162float(h1.x));
        lo1.y = __float2bfloat16_rn(v11 - __bfloat162float(h1.y));
        *(__nv_bfloat162*)(g_aohi + ro0 + d) = h0;
        *(__nv_bfloat162*)(g_aohi + ro1 + d) = h1;
        *(__nv_bfloat162*)(g_aolo + ro0 + d) = lo0;
        *(__nv_bfloat162*)(g_aolo + ro1 + d) = lo1;
    }
}

// ---------------- launch ----------------
extern "C" void kernel_launch(void* const* d_in, const int* in_sizes, int n_in,
                              void* d_out, int out_size) {
    const float* x  = (const float*)d_in[0];
    const float* ts = (const float*)d_in[1];
    const float* Wq = (const float*)d_in[2];
    const float* bq = (const float*)d_in[3];
    const float* Wk = (const float*)d_in[4];
    const float* bk = (const float*)d_in[5];
    const float* Wv = (const float*)d_in[6];
    const float* bv = (const float*)d_in[7];
    const float* Wo = (const float*)d_in[8];
    const float* bo = (const float*)d_in[9];
    const float* td = (const float*)d_in[10];
    float* out = (float*)d_out;

    __nv_bfloat16 *xhi, *xlo, *wthi, *wtlo;
    cudaGetSymbolAddress((void**)&xhi,  g_xhi);
    cudaGetSymbolAddress((void**)&xlo,  g_xlo);
    cudaGetSymbolAddress((void**)&wthi, g_wthi);
    cudaGetSymbolAddress((void**)&wtlo, g_wtlo);

    static int attr_done = 0;
    if (!attr_done) {
        cudaFuncSetAttribute(gemm_qkv, cudaFuncAttributeMaxDynamicSharedMemorySize, G_SMEM);
        cudaFuncSetAttribute(gemm_o,   cudaFuncAttributeMaxDynamicSharedMemorySize, G_SMEM);
        cudaFuncSetAttribute(attn_mma, cudaFuncAttributeMaxDynamicSharedMemorySize, A_SMEM);
        attr_done = 1;
    }

    prep_kernel<<<M_ / 256, 256>>>(ts, td);
    split_kernel<<<(M_ * D_) / 256, 256>>>(x, xhi, xlo);
    transpose_split_all<<<dim3(D_ / 32, D_ / 32, 4), dim3(32, 8)>>>(Wq, Wk, Wv, Wo, wthi, wtlo);

    gemm_qkv<<<dim3(D_ / 128, M_ / 128, 3), 256, G_SMEM>>>(bq, bk, bv);
    attn_mma<<<dim3(S_ / 64, H_, B_), 128, A_SMEM>>>();
    gemm_o<<<dim3(D_ / 128, M_ / 128), 256, G_SMEM>>>(bo, out);
}

// round 13
// speedup vs baseline: 1.0694x; 1.0694x over previous
#include <cuda_runtime.h>
#include <cuda_bf16.h>
#include <math.h>
#include <cstdint>

#define B_  2
#define S_  2048
#define D_  1024
#define H_  16
#define HD_ 64
#define M_  (B_*S_)

// ---------------- scratch (no allocs allowed) ----------------
__device__ float g_E[M_], g_R[M_];
__device__ __nv_bfloat16 g_xhi [M_*D_], g_xlo [M_*D_];
__device__ __nv_bfloat16 g_qhi [M_*D_], g_qlo [M_*D_];
__device__ __nv_bfloat16 g_khi [M_*D_], g_klo [M_*D_];
__device__ __nv_bfloat16 g_vhi [M_*D_], g_vlo [M_*D_];
__device__ __nv_bfloat16 g_aohi[M_*D_], g_aolo[M_*D_];
__device__ __nv_bfloat16 g_wthi[4u*D_*D_], g_wtlo[4u*D_*D_];

// ================= helpers =================
__device__ __forceinline__ uint32_t smem_u32(const void* p) {
    uint32_t a;
    asm("{ .reg .u64 t; cvta.to.shared.u64 t, %1; cvt.u32.u64 %0, t; }" : "=r"(a) : "l"(p));
    return a;
}
__device__ __forceinline__ void ldsm4(uint32_t* r, uint32_t a) {
    asm volatile("ldmatrix.sync.aligned.m8n8.x4.shared.b16 {%0,%1,%2,%3}, [%4];"
        : "=r"(r[0]), "=r"(r[1]), "=r"(r[2]), "=r"(r[3]) : "r"(a));
}
__device__ __forceinline__ void ldsm4t(uint32_t* r, uint32_t a) {
    asm volatile("ldmatrix.sync.aligned.m8n8.x4.trans.shared.b16 {%0,%1,%2,%3}, [%4];"
        : "=r"(r[0]), "=r"(r[1]), "=r"(r[2]), "=r"(r[3]) : "r"(a));
}
__device__ __forceinline__ void mma_bf16(float* c, const uint32_t* a, const uint32_t* b) {
    asm volatile("mma.sync.aligned.m16n8k16.row.col.f32.bf16.bf16.f32 "
        "{%0,%1,%2,%3}, {%4,%5,%6,%7}, {%8,%9}, {%0,%1,%2,%3};"
        : "+f"(c[0]), "+f"(c[1]), "+f"(c[2]), "+f"(c[3])
        : "r"(a[0]), "r"(a[1]), "r"(a[2]), "r"(a[3]), "r"(b[0]), "r"(b[1]));
}
__device__ __forceinline__ uint32_t pack2(float lo, float hi) {
    uint32_t r;
    asm("cvt.rn.bf16x2.f32 %0, %1, %2;" : "=r"(r) : "f"(hi), "f"(lo));
    return r;
}
__device__ __forceinline__ float bf16x2_lo(uint32_t v) { return __uint_as_float(v << 16); }
__device__ __forceinline__ float bf16x2_hi(uint32_t v) { return __uint_as_float(v & 0xffff0000u); }

#define CP16(dst, src) asm volatile("cp.async.cg.shared.global [%0], [%1], 16;" :: "r"(dst), "l"(src))
#define CP_COMMIT()    asm volatile("cp.async.commit_group;" ::: "memory")
#define CP_WAIT0()     asm volatile("cp.async.wait_group 0;" ::: "memory")

// FFMA-only exp (x <= 0 expected)
__device__ __forceinline__ float fast_exp(float x) {
    x = fmaxf(x, -80.0f);
    float t = x * 1.4426950408889634f;
    float z = t + 12582912.0f;
    int  ni = __float_as_int(z) - 0x4B400000;
    float n = z - 12582912.0f;
    float g = fmaf(n, -0.6931471805599453f, x);
    float p = 1.3888889e-3f;
    p = fmaf(p, g, 8.3333333e-3f);
    p = fmaf(p, g, 4.1666667e-2f);
    p = fmaf(p, g, 1.6666667e-1f);
    p = fmaf(p, g, 0.5f);
    p = fmaf(p, g, 1.0f);
    p = fmaf(p, g, 1.0f);
    return p * __int_as_float((ni + 127) << 23);
}

// ---------------- small prep kernels ----------------
__global__ void prep_kernel(const float* __restrict__ ts, const float* __restrict__ td) {
    int i = blockIdx.x * 256 + threadIdx.x;
    if (i < M_) {
        float e = expf(td[0] * ts[i]);
        g_E[i] = e;
        g_R[i] = 1.0f / e;
    }
}
__global__ __launch_bounds__(256) void split_kernel(const float* __restrict__ src,
                                                    __nv_bfloat16* __restrict__ hi,
                                                    __nv_bfloat16* __restrict__ lo) {
    int i = blockIdx.x * 256 + threadIdx.x;
    float f = src[i];
    __nv_bfloat16 h = __float2bfloat16_rn(f);
    hi[i] = h;
    lo[i] = __float2bfloat16_rn(f - __bfloat162float(h));
}
__global__ __launch_bounds__(256) void transpose_split_all(
    const float* __restrict__ W0, const float* __restrict__ W1,
    const float* __restrict__ W2, const float* __restrict__ W3,
    __nv_bfloat16* __restrict__ hi, __nv_bfloat16* __restrict__ lo)
{
    __shared__ float tile[32][33];
    int z = blockIdx.z;
    const float* W = (z == 0) ? W0 : (z == 1) ? W1 : (z == 2) ? W2 : W3;
    size_t zoff = (size_t)z * D_ * D_;
    int tx = threadIdx.x, ty = threadIdx.y;
    int n0 = blockIdx.x * 32, k0 = blockIdx.y * 32;
#pragma unroll
    for (int j = 0; j < 32; j += 8)
        tile[ty + j][tx] = W[(size_t)(k0 + ty + j) * D_ + n0 + tx];
    __syncthreads();
#pragma unroll
    for (int j = 0; j < 32; j += 8) {
        float f = tile[tx][ty + j];
        __nv_bfloat16 h = __float2bfloat16_rn(f);
        size_t o = zoff + (size_t)(n0 + ty + j) * D_ + k0 + tx;
        hi[o] = h;
        lo[o] = __float2bfloat16_rn(f - __bfloat162float(h));
    }
}

// ---------------- HMMA split-bf16 GEMM core (cp.async 2-stage, 2 CTA/SM) ----------------
static constexpr int G_STAGE = 40960;
static constexpr int G_SMEM  = 2 * G_STAGE;

__device__ __forceinline__ void gemm_issue_chunk(
    uint32_t sb, int stage,
    const __nv_bfloat16* Ahi, const __nv_bfloat16* Alo,
    const __nv_bfloat16* Bhi, const __nv_bfloat16* Blo,
    int m0, int n0, int k0, int tid)
{
    uint32_t st = sb + stage * G_STAGE;
#pragma unroll
    for (int j = 0; j < 8; j++) {
        int rem = tid + (j & 1) * 256;
        int r = rem >> 2, c4 = rem & 3;
        const __nv_bfloat16* base = (j < 2) ? Ahi : (j < 4) ? Alo : (j < 6) ? Bhi : Blo;
        int rowbase = (j < 4) ? m0 : n0;
        uint32_t dst = st + (uint32_t)(j >> 1) * 10240u + (uint32_t)(r * 80 + c4 * 16);
        const __nv_bfloat16* src = base + (size_t)(rowbase + r) * D_ + k0 + c4 * 8;
        CP16(dst, src);
    }
    CP_COMMIT();
}

template<int MODE>   // 0: fp32 out, 1: split-bf16 out
__device__ __forceinline__ void gemm_body(
    const __nv_bfloat16* Ahi, const __nv_bfloat16* Alo,
    const __nv_bfloat16* Bhi, const __nv_bfloat16* Blo,
    const float* bias, float scale,
    float* Cf, __nv_bfloat16* Chi, __nv_bfloat16* Clo, char* smem)
{
    uint32_t sb = smem_u32(smem);
    int tid = threadIdx.x, l = tid & 31, wid = tid >> 5;
    int wm = wid >> 2, wn = wid & 3;
    int m0 = blockIdx.y * 128, n0 = blockIdx.x * 128;

    float acc[4][4][4];
#pragma unroll
    for (int a = 0; a < 4; a++)
#pragma unroll
        for (int b2 = 0; b2 < 4; b2++)
#pragma unroll
            for (int c = 0; c < 4; c++) acc[a][b2][c] = 0.f;

    gemm_issue_chunk(sb, 0, Ahi, Alo, Bhi, Blo, m0, n0, 0, tid);

    for (int kc = 0; kc < 32; kc++) {
        CP_WAIT0();
        __syncthreads();
        if (kc + 1 < 32)
            gemm_issue_chunk(sb, (kc + 1) & 1, Ahi, Alo, Bhi, Blo, m0, n0, (kc + 1) * 32, tid);

        uint32_t st  = sb + (kc & 1) * G_STAGE;
        uint32_t bAh = st, bAl = st + 10240, bBh = st + 20480, bBl = st + 30720;
#pragma unroll
        for (int s = 0; s < 2; s++) {
            int k0 = s * 16;
            uint32_t ah[4][4], al[4][4], bh[2][4], bl[2][4];
#pragma unroll
            for (int mi = 0; mi < 4; mi++) {
                int row = wm * 64 + mi * 16 + (l & 15);
                int col = k0 + ((l >> 4) << 3);
                uint32_t off = (uint32_t)(row * 40 + col) * 2;
                ldsm4(ah[mi], bAh + off);
                ldsm4(al[mi], bAl + off);
            }
#pragma unroll
            for (int np = 0; np < 2; np++) {
                int row = wn * 32 + np * 16 + (l & 7) + ((l >> 4) << 3);
                int col = k0 + (((l >> 3) & 1) << 3);
                uint32_t off = (uint32_t)(row * 40 + col) * 2;
                ldsm4(bh[np], bBh + off);
                ldsm4(bl[np], bBl + off);
            }
#pragma unroll
            for (int mi = 0; mi < 4; mi++)
#pragma unroll
                for (int ni = 0; ni < 4; ni++)
                    mma_bf16(acc[mi][ni], ah[mi], &bh[ni >> 1][(ni & 1) * 2]);
#pragma unroll
            for (int mi = 0; mi < 4; mi++)
#pragma unroll
                for (int ni = 0; ni < 4; ni++)
                    mma_bf16(acc[mi][ni], ah[mi], &bl[ni >> 1][(ni & 1) * 2]);
#pragma unroll
            for (int mi = 0; mi < 4; mi++)
#pragma unroll
                for (int ni = 0; ni < 4; ni++)
                    mma_bf16(acc[mi][ni], al[mi], &bh[ni >> 1][(ni & 1) * 2]);
        }
    }
    // epilogue
#pragma unroll
    for (int mi = 0; mi < 4; mi++) {
        int row0 = m0 + wm * 64 + mi * 16 + (l >> 2);
#pragma unroll
        for (int ni = 0; ni < 4; ni++) {
            int col = n0 + wn * 32 + ni * 8 + ((l & 3) << 1);
            float b0 = bias[col], b1 = bias[col + 1];
            float v00 = (acc[mi][ni][0] + b0) * scale;
            float v01 = (acc[mi][ni][1] + b1) * scale;
            float v10 = (acc[mi][ni][2] + b0) * scale;
            float v11 = (acc[mi][ni][3] + b1) * scale;
            size_t o0 = (size_t)row0 * D_ + col;
            size_t o1 = o0 + (size_t)8 * D_;
            if (MODE == 0) {
                *(float2*)(Cf + o0) = make_float2(v00, v01);
                *(float2*)(Cf + o1) = make_float2(v10, v11);
            } else {
                __nv_bfloat162 h0, h1, l0p, l1p;
                h0.x = __float2bfloat16_rn(v00); h0.y = __float2bfloat16_rn(v01);
                h1.x = __float2bfloat16_rn(v10); h1.y = __float2bfloat16_rn(v11);
                l0p.x = __float2bfloat16_rn(v00 - __bfloat162float(h0.x));
                l0p.y = __float2bfloat16_rn(v01 - __bfloat162float(h0.y));
                l1p.x = __float2bfloat16_rn(v10 - __bfloat162float(h1.x));
                l1p.y = __float2bfloat16_rn(v11 - __bfloat162float(h1.y));
                *(__nv_bfloat162*)(Chi + o0) = h0;
                *(__nv_bfloat162*)(Chi + o1) = h1;
                *(__nv_bfloat162*)(Clo + o0) = l0p;
                *(__nv_bfloat162*)(Clo + o1) = l1p;
            }
        }
    }
}

// __launch_bounds__(256, 2): cap at 128 regs so 2 CTAs fit the 64K register file
__global__ __launch_bounds__(256, 2) void gemm_qkv(
    const float* __restrict__ bq, const float* __restrict__ bk, const float* __restrict__ bv)
{
    extern __shared__ char smem[];
    int z = blockIdx.z;
    const size_t WSZ = (size_t)D_ * D_;
    const __nv_bfloat16* Bh = g_wthi + (size_t)z * WSZ;
    const __nv_bfloat16* Bl = g_wtlo + (size_t)z * WSZ;
    const float* bias = (z == 0) ? bq : (z == 1) ? bk : bv;
    __nv_bfloat16* Chi = (z == 0) ? g_qhi : (z == 1) ? g_khi : g_vhi;
    __nv_bfloat16* Clo = (z == 0) ? g_qlo : (z == 1) ? g_klo : g_vlo;
    float scale = (z == 0) ? 0.125f : 1.0f;
    gemm_body<1>(g_xhi, g_xlo, Bh, Bl, bias, scale, nullptr, Chi, Clo, smem);
}

__global__ __launch_bounds__(256, 2) void gemm_o(const float* __restrict__ bo, float* __restrict__ out)
{
    extern __shared__ char smem[];
    const size_t WSZ = (size_t)D_ * D_;
    gemm_body<0>(g_aohi, g_aolo, g_wthi + 3 * WSZ, g_wtlo + 3 * WSZ, bo, 1.0f, out, nullptr, nullptr, smem);
}

// ---------------- HMMA flash attention (cp.async 2-stage) ----------------
static constexpr int A_STAGE = 37376;
static constexpr int A_SMEM  = 2 * A_STAGE;

__device__ __forceinline__ void attn_issue_tile(uint32_t sb, int stage, int b, int h, int kt, int tid) {
    uint32_t st = sb + stage * A_STAGE;
#pragma unroll
    for (int j = 0; j < 16; j++) {
        int a = j >> 2;
        int rem = tid + (j & 3) * 128;
        int r = rem >> 3, c = rem & 7;
        const __nv_bfloat16* base = (a == 0) ? g_khi : (a == 1) ? g_klo : (a == 2) ? g_vhi : g_vlo;
        uint32_t dst = st + (uint32_t)a * 9216u + (uint32_t)(r * 144 + c * 16);
        const __nv_bfloat16* src = base + (size_t)(b * S_ + kt + r) * D_ + h * HD_ + c * 8;
        CP16(dst, src);
    }
    if (tid < 16)      CP16(st + 36864u + tid * 16, &g_E[b * S_ + kt + tid * 4]);
    else if (tid < 32) CP16(st + 37120u + (tid - 16) * 16, &g_R[b * S_ + kt + (tid - 16) * 4]);
    CP_COMMIT();
}

__global__ __launch_bounds__(128) void attn_mma() {
    extern __shared__ char smem[];
    uint32_t sb = smem_u32(smem);
    int tid = threadIdx.x, l = tid & 31, wid = tid >> 5;
    int h = blockIdx.y, b = blockIdx.z;
    int q0 = blockIdx.x * 64;

    // ---- stage Q (hi then lo) through stage-0 region, pull frags ----
    __nv_bfloat16* qstage = (__nv_bfloat16*)smem;
    uint32_t bQ = sb;
    uint32_t qh[4][4], ql[4][4];
#pragma unroll
    for (int t = 0; t < 4; t++) {
        int i = tid + t * 128;
        int r = i >> 3, c8 = (i & 7) << 3;
        *(uint4*)(qstage + r * 72 + c8) =
            *(const uint4*)(g_qhi + (size_t)(b * S_ + q0 + r) * D_ + h * HD_ + c8);
    }
    __syncthreads();
#pragma unroll
    for (int ks = 0; ks < 4; ks++) {
        int row = wid * 16 + (l & 15);
        int col = ks * 16 + ((l >> 4) << 3);
        ldsm4(qh[ks], bQ + (uint32_t)(row * 72 + col) * 2);
    }
    __syncthreads();
#pragma unroll
    for (int t = 0; t < 4; t++) {
        int i = tid + t * 128;
        int r = i >> 3, c8 = (i & 7) << 3;
        *(uint4*)(qstage + r * 72 + c8) =
            *(const uint4*)(g_qlo + (size_t)(b * S_ + q0 + r) * D_ + h * HD_ + c8);
    }
    __syncthreads();
#pragma unroll
    for (int ks = 0; ks < 4; ks++) {
        int row = wid * 16 + (l & 15);
        int col = ks * 16 + ((l >> 4) << 3);
        ldsm4(ql[ks], bQ + (uint32_t)(row * 72 + col) * 2);
    }
    __syncthreads();

    int r0 = wid * 16 + (l >> 2), r1 = r0 + 8;
    float Ei0 = g_E[b * S_ + q0 + r0], Ri0 = g_R[b * S_ + q0 + r0];
    float Ei1 = g_E[b * S_ + q0 + r1], Ri1 = g_R[b * S_ + q0 + r1];

    float Oa[8][4];
#pragma unroll
    for (int f = 0; f < 8; f++)
#pragma unroll
        for (int c = 0; c < 4; c++) Oa[f][c] = 0.f;
    float m0v = -1e30f, m1v = -1e30f, l0v = 0.f, l1v = 0.f;

    attn_issue_tile(sb, 0, b, h, 0, tid);

    for (int t = 0; t < S_ / 64; t++) {
        CP_WAIT0();
        __syncthreads();
        if (t + 1 < S_ / 64)
            attn_issue_tile(sb, (t + 1) & 1, b, h, (t + 1) * 64, tid);

        uint32_t st  = sb + (t & 1) * A_STAGE;
        uint32_t bKh = st, bKl = st + 9216, bVh = st + 18432, bVl = st + 27648;
        const float* sE = (const float*)(smem + (t & 1) * A_STAGE + 36864);
        const float* sR = (const float*)(smem + (t & 1) * A_STAGE + 37120);

        // scores: S = qhi.Khi + qhi.Klo + qlo.Khi
        float Sa[8][4];
#pragma unroll
        for (int f = 0; f < 8; f++)
#pragma unroll
            for (int c = 0; c < 4; c++) Sa[f][c] = 0.f;
#pragma unroll
        for (int ks = 0; ks < 4; ks++) {
            uint32_t kh[4][4], kl[4][4];
#pragma unroll
            for (int g2 = 0; g2 < 4; g2++) {
                int row = g2 * 16 + (l & 7) + ((l >> 4) << 3);
                int col = ks * 16 + (((l >> 3) & 1) << 3);
                uint32_t off = (uint32_t)(row * 72 + col) * 2;
                ldsm4(kh[g2], bKh + off);
                ldsm4(kl[g2], bKl + off);
            }
#pragma unroll
            for (int f = 0; f < 8; f++)
                mma_bf16(Sa[f], qh[ks], &kh[f >> 1][(f & 1) * 2]);
#pragma unroll
            for (int f = 0; f < 8; f++)
                mma_bf16(Sa[f], qh[ks], &kl[f >> 1][(f & 1) * 2]);
#pragma unroll
            for (int f = 0; f < 8; f++)
                mma_bf16(Sa[f], ql[ks], &kh[f >> 1][(f & 1) * 2]);
        }

        // decay + tile max
        int c0 = (l & 3) << 1;
        float mx0 = -1e30f, mx1 = -1e30f;
#pragma unroll
        for (int f = 0; f < 8; f++) {
            int j = f * 8 + c0;
            float Ej0 = sE[j], Rj0 = sR[j], Ej1 = sE[j + 1], Rj1 = sR[j + 1];
            Sa[f][0] *= fminf(Ei0 * Rj0, Ej0 * Ri0);
            Sa[f][1] *= fminf(Ei0 * Rj1, Ej1 * Ri0);
            Sa[f][2] *= fminf(Ei1 * Rj0, Ej0 * Ri1);
            Sa[f][3] *= fminf(Ei1 * Rj1, Ej1 * Ri1);
            mx0 = fmaxf(mx0, fmaxf(Sa[f][0], Sa[f][1]));
            mx1 = fmaxf(mx1, fmaxf(Sa[f][2], Sa[f][3]));
        }
        mx0 = fmaxf(mx0, __shfl_xor_sync(0xffffffffu, mx0, 1));
        mx0 = fmaxf(mx0, __shfl_xor_sync(0xffffffffu, mx0, 2));
        mx1 = fmaxf(mx1, __shfl_xor_sync(0xffffffffu, mx1, 1));
        mx1 = fmaxf(mx1, __shfl_xor_sync(0xffffffffu, mx1, 2));

        float mn0 = fmaxf(m0v, mx0), mn1 = fmaxf(m1v, mx1);
        float sc0 = fast_exp(m0v - mn0), sc1 = fast_exp(m1v - mn1);
        m0v = mn0; m1v = mn1;
        l0v *= sc0; l1v *= sc1;
#pragma unroll
        for (int f = 0; f < 8; f++) {
            Oa[f][0] *= sc0; Oa[f][1] *= sc0;
            Oa[f][2] *= sc1; Oa[f][3] *= sc1;
        }

        // p = exp(s - m), split into bf16 hi/lo A-frags
        uint32_t Ph[8][2], Pl[8][2];
        float rs0 = 0.f, rs1 = 0.f;
#pragma unroll
        for (int f = 0; f < 8; f++) {
            float p00 = fast_exp(Sa[f][0] - mn0);
            float p01 = fast_exp(Sa[f][1] - mn0);
            float p10 = fast_exp(Sa[f][2] - mn1);
            float p11 = fast_exp(Sa[f][3] - mn1);
            rs0 += p00 + p01; rs1 += p10 + p11;
            uint32_t h0 = pack2(p00, p01);
            uint32_t h1 = pack2(p10, p11);
            Ph[f][0] = h0; Ph[f][1] = h1;
            Pl[f][0] = pack2(p00 - bf16x2_lo(h0), p01 - bf16x2_hi(h0));
            Pl[f][1] = pack2(p10 - bf16x2_lo(h1), p11 - bf16x2_hi(h1));
        }
        rs0 += __shfl_xor_sync(0xffffffffu, rs0, 1);
        rs0 += __shfl_xor_sync(0xffffffffu, rs0, 2);
        rs1 += __shfl_xor_sync(0xffffffffu, rs1, 1);
        rs1 += __shfl_xor_sync(0xffffffffu, rs1, 2);
        l0v += rs0; l1v += rs1;

        // O += Phi.Vhi + Phi.Vlo + Plo.Vhi
#pragma unroll
        for (int ks = 0; ks < 4; ks++) {
            uint32_t pah[4] = {Ph[2*ks][0], Ph[2*ks][1], Ph[2*ks+1][0], Ph[2*ks+1][1]};
            uint32_t pal[4] = {Pl[2*ks][0], Pl[2*ks][1], Pl[2*ks+1][0], Pl[2*ks+1][1]};
            uint32_t vh[4][4], vl[4][4];
#pragma unroll
            for (int db = 0; db < 4; db++) {
                int row = ks * 16 + (l & 7) + (((l >> 3) & 1) << 3);
                int col = db * 16 + ((l >> 4) << 3);
                uint32_t off = (uint32_t)(row * 72 + col) * 2;
                ldsm4t(vh[db], bVh + off);
                ldsm4t(vl[db], bVl + off);
            }
#pragma unroll
            for (int db = 0; db < 4; db++) {
                mma_bf16(Oa[2*db],   pah, &vh[db][0]);
                mma_bf16(Oa[2*db+1], pah, &vh[db][2]);
            }
#pragma unroll
            for (int db = 0; db < 4; db++) {
                mma_bf16(Oa[2*db],   pah, &vl[db][0]);
                mma_bf16(Oa[2*db+1], pah, &vl[db][2]);
            }
#pragma unroll
            for (int db = 0; db < 4; db++) {
                mma_bf16(Oa[2*db],   pal, &vh[db][0]);
                mma_bf16(Oa[2*db+1], pal, &vh[db][2]);
            }
        }
    }

    // normalize + split-write ao
    float inv0 = 1.0f / l0v, inv1 = 1.0f / l1v;
    int c0 = (l & 3) << 1;
    size_t ro0 = (size_t)(b * S_ + q0 + r0) * D_ + h * HD_;
    size_t ro1 = (size_t)(b * S_ + q0 + r1) * D_ + h * HD_;
#pragma unroll
    for (int f = 0; f < 8; f++) {
        int d = f * 8 + c0;
        float v00 = Oa[f][0] * inv0, v01 = Oa[f][1] * inv0;
        float v10 = Oa[f][2] * inv1, v11 = Oa[f][3] * inv1;
        __nv_bfloat162 h0, h1, lo0, lo1;
        h0.x = __float2bfloat16_rn(v00); h0.y = __float2bfloat16_rn(v01);
        h1.x = __float2bfloat16_rn(v10); h1.y = __float2bfloat16_rn(v11);
        lo0.x = __float2bfloat16_rn(v00 - __bfloat162float(h0.x));
        lo0.y = __float2bfloat16_rn(v01 - __bfloat162float(h0.y));
        lo1.x = __float2bfloat16_rn(v10 - __bfloat162float(h1.x));
        lo1.y = __float2bfloat16_rn(v11 - __bfloat162float(h1.y));
        *(__nv_bfloat162*)(g_aohi + ro0 + d) = h0;
        *(__nv_bfloat162*)(g_aohi + ro1 + d) = h1;
        *(__nv_bfloat162*)(g_aolo + ro0 + d) = lo0;
        *(__nv_bfloat162*)(g_aolo + ro1 + d) = lo1;
    }
}

// ---------------- launch ----------------
extern "C" void kernel_launch(void* const* d_in, const int* in_sizes, int n_in,
                              void* d_out, int out_size) {
    const float* x  = (const float*)d_in[0];
    const float* ts = (const float*)d_in[1];
    const float* Wq = (const float*)d_in[2];
    const float* bq = (const float*)d_in[3];
    const float* Wk = (const float*)d_in[4];
    const float* bk = (const float*)d_in[5];
    const float* Wv = (const float*)d_in[6];
    const float* bv = (const float*)d_in[7];
    const float* Wo = (const float*)d_in[8];
    const float* bo = (const float*)d_in[9];
    const float* td = (const float*)d_in[10];
    float* out = (float*)d_out;

    __nv_bfloat16 *xhi, *xlo, *wthi, *wtlo;
    cudaGetSymbolAddress((void**)&xhi,  g_xhi);
    cudaGetSymbolAddress((void**)&xlo,  g_xlo);
    cudaGetSymbolAddress((void**)&wthi, g_wthi);
    cudaGetSymbolAddress((void**)&wtlo, g_wtlo);

    static int attr_done = 0;
    if (!attr_done) {
        cudaFuncSetAttribute(gemm_qkv, cudaFuncAttributeMaxDynamicSharedMemorySize, G_SMEM);
        cudaFuncSetAttribute(gemm_o,   cudaFuncAttributeMaxDynamicSharedMemorySize, G_SMEM);
        cudaFuncSetAttribute(attn_mma, cudaFuncAttributeMaxDynamicSharedMemorySize, A_SMEM);
        attr_done = 1;
    }

    prep_kernel<<<M_ / 256, 256>>>(ts, td);
    split_kernel<<<(M_ * D_) / 256, 256>>>(x, xhi, xlo);
    transpose_split_all<<<dim3(D_ / 32, D_ / 32, 4), dim3(32, 8)>>>(Wq, Wk, Wv, Wo, wthi, wtlo);

    gemm_qkv<<<dim3(D_ / 128, M_ / 128, 3), 256, G_SMEM>>>(bq, bk, bv);
    attn_mma<<<dim3(S_ / 64, H_, B_), 128, A_SMEM>>>();
    gemm_o<<<dim3(D_ / 128, M_ / 128), 256, G_SMEM>>>(bo, out);
}

// round 14
// speedup vs baseline: 1.2779x; 1.1950x over previous
#include <cuda_runtime.h>
#include <cuda_bf16.h>
#include <cuda_fp16.h>
#include <math.h>
#include <cstdint>

#define B_  2
#define S_  2048
#define D_  1024
#define H_  16
#define HD_ 64
#define M_  (B_*S_)

// ---------------- scratch (no allocs allowed) ----------------
__device__ float g_E[M_], g_R[M_];
__device__ __nv_bfloat16 g_xhi [M_*D_], g_xlo [M_*D_];
__device__ __half        g_qf  [M_*D_];               // q, fp16 single (1/8 folded)
__device__ __half        g_kf  [M_*D_];               // k, fp16 single
__device__ __half        g_vh  [M_*D_], g_vl [M_*D_]; // v, fp16 hi/lo split
__device__ __nv_bfloat16 g_aohi[M_*D_], g_aolo[M_*D_];
__device__ __nv_bfloat16 g_wthi[4u*D_*D_], g_wtlo[4u*D_*D_];

// ================= helpers =================
__device__ __forceinline__ uint32_t smem_u32(const void* p) {
    uint32_t a;
    asm("{ .reg .u64 t; cvta.to.shared.u64 t, %1; cvt.u32.u64 %0, t; }" : "=r"(a) : "l"(p));
    return a;
}
__device__ __forceinline__ void ldsm4(uint32_t* r, uint32_t a) {
    asm volatile("ldmatrix.sync.aligned.m8n8.x4.shared.b16 {%0,%1,%2,%3}, [%4];"
        : "=r"(r[0]), "=r"(r[1]), "=r"(r[2]), "=r"(r[3]) : "r"(a));
}
__device__ __forceinline__ void ldsm4t(uint32_t* r, uint32_t a) {
    asm volatile("ldmatrix.sync.aligned.m8n8.x4.trans.shared.b16 {%0,%1,%2,%3}, [%4];"
        : "=r"(r[0]), "=r"(r[1]), "=r"(r[2]), "=r"(r[3]) : "r"(a));
}
__device__ __forceinline__ void mma_bf16(float* c, const uint32_t* a, const uint32_t* b) {
    asm volatile("mma.sync.aligned.m16n8k16.row.col.f32.bf16.bf16.f32 "
        "{%0,%1,%2,%3}, {%4,%5,%6,%7}, {%8,%9}, {%0,%1,%2,%3};"
        : "+f"(c[0]), "+f"(c[1]), "+f"(c[2]), "+f"(c[3])
        : "r"(a[0]), "r"(a[1]), "r"(a[2]), "r"(a[3]), "r"(b[0]), "r"(b[1]));
}
__device__ __forceinline__ void mma_f16(float* c, const uint32_t* a, const uint32_t* b) {
    asm volatile("mma.sync.aligned.m16n8k16.row.col.f32.f16.f16.f32 "
        "{%0,%1,%2,%3}, {%4,%5,%6,%7}, {%8,%9}, {%0,%1,%2,%3};"
        : "+f"(c[0]), "+f"(c[1]), "+f"(c[2]), "+f"(c[3])
        : "r"(a[0]), "r"(a[1]), "r"(a[2]), "r"(a[3]), "r"(b[0]), "r"(b[1]));
}
// pack (lo, hi) floats into f16x2 (lo -> bits[15:0])
__device__ __forceinline__ uint32_t pack2h(float lo, float hi) {
    uint32_t r;
    asm("cvt.rn.f16x2.f32 %0, %1, %2;" : "=r"(r) : "f"(hi), "f"(lo));
    return r;
}

#define CP16(dst, src) asm volatile("cp.async.cg.shared.global [%0], [%1], 16;" :: "r"(dst), "l"(src))
#define CP_COMMIT()    asm volatile("cp.async.commit_group;" ::: "memory")
#define CP_WAIT0()     asm volatile("cp.async.wait_group 0;" ::: "memory")

// FFMA-only exp (x <= 0 expected)
__device__ __forceinline__ float fast_exp(float x) {
    x = fmaxf(x, -80.0f);
    float t = x * 1.4426950408889634f;
    float z = t + 12582912.0f;
    int  ni = __float_as_int(z) - 0x4B400000;
    float n = z - 12582912.0f;
    float g = fmaf(n, -0.6931471805599453f, x);
    float p = 1.3888889e-3f;
    p = fmaf(p, g, 8.3333333e-3f);
    p = fmaf(p, g, 4.1666667e-2f);
    p = fmaf(p, g, 1.6666667e-1f);
    p = fmaf(p, g, 0.5f);
    p = fmaf(p, g, 1.0f);
    p = fmaf(p, g, 1.0f);
    return p * __int_as_float((ni + 127) << 23);
}

// ---------------- small prep kernels ----------------
__global__ void prep_kernel(const float* __restrict__ ts, const float* __restrict__ td) {
    int i = blockIdx.x * 256 + threadIdx.x;
    if (i < M_) {
        float e = expf(td[0] * ts[i]);
        g_E[i] = e;
        g_R[i] = 1.0f / e;
    }
}
__global__ __launch_bounds__(256) void split_kernel(const float* __restrict__ src,
                                                    __nv_bfloat16* __restrict__ hi,
                                                    __nv_bfloat16* __restrict__ lo) {
    int i = blockIdx.x * 256 + threadIdx.x;
    float f = src[i];
    __nv_bfloat16 h = __float2bfloat16_rn(f);
    hi[i] = h;
    lo[i] = __float2bfloat16_rn(f - __bfloat162float(h));
}
__global__ __launch_bounds__(256) void transpose_split_all(
    const float* __restrict__ W0, const float* __restrict__ W1,
    const float* __restrict__ W2, const float* __restrict__ W3,
    __nv_bfloat16* __restrict__ hi, __nv_bfloat16* __restrict__ lo)
{
    __shared__ float tile[32][33];
    int z = blockIdx.z;
    const float* W = (z == 0) ? W0 : (z == 1) ? W1 : (z == 2) ? W2 : W3;
    size_t zoff = (size_t)z * D_ * D_;
    int tx = threadIdx.x, ty = threadIdx.y;
    int n0 = blockIdx.x * 32, k0 = blockIdx.y * 32;
#pragma unroll
    for (int j = 0; j < 32; j += 8)
        tile[ty + j][tx] = W[(size_t)(k0 + ty + j) * D_ + n0 + tx];
    __syncthreads();
#pragma unroll
    for (int j = 0; j < 32; j += 8) {
        float f = tile[tx][ty + j];
        __nv_bfloat16 h = __float2bfloat16_rn(f);
        size_t o = zoff + (size_t)(n0 + ty + j) * D_ + k0 + tx;
        hi[o] = h;
        lo[o] = __float2bfloat16_rn(f - __bfloat162float(h));
    }
}

// ---------------- HMMA split-bf16 GEMM core (cp.async 2-stage, 2 CTA/SM) ----------------
static constexpr int G_STAGE = 40960;
static constexpr int G_SMEM  = 2 * G_STAGE;

__device__ __forceinline__ void gemm_issue_chunk(
    uint32_t sb, int stage,
    const __nv_bfloat16* Ahi, const __nv_bfloat16* Alo,
    const __nv_bfloat16* Bhi, const __nv_bfloat16* Blo,
    int m0, int n0, int k0, int tid)
{
    uint32_t st = sb + stage * G_STAGE;
#pragma unroll
    for (int j = 0; j < 8; j++) {
        int rem = tid + (j & 1) * 256;
        int r = rem >> 2, c4 = rem & 3;
        const __nv_bfloat16* base = (j < 2) ? Ahi : (j < 4) ? Alo : (j < 6) ? Bhi : Blo;
        int rowbase = (j < 4) ? m0 : n0;
        uint32_t dst = st + (uint32_t)(j >> 1) * 10240u + (uint32_t)(r * 80 + c4 * 16);
        const __nv_bfloat16* src = base + (size_t)(rowbase + r) * D_ + k0 + c4 * 8;
        CP16(dst, src);
    }
    CP_COMMIT();
}

// mode: 0 fp32 out, 1 fp16 single out, 2 fp16 split out
__device__ __forceinline__ void gemm_body(
    const __nv_bfloat16* Ahi, const __nv_bfloat16* Alo,
    const __nv_bfloat16* Bhi, const __nv_bfloat16* Blo,
    const float* bias, float scale, int mode,
    float* Cf, __half* H0, __half* H1, char* smem)
{
    uint32_t sb = smem_u32(smem);
    int tid = threadIdx.x, l = tid & 31, wid = tid >> 5;
    int wm = wid >> 2, wn = wid & 3;
    int m0 = blockIdx.y * 128, n0 = blockIdx.x * 128;

    float acc[4][4][4];
#pragma unroll
    for (int a = 0; a < 4; a++)
#pragma unroll
        for (int b2 = 0; b2 < 4; b2++)
#pragma unroll
            for (int c = 0; c < 4; c++) acc[a][b2][c] = 0.f;

    gemm_issue_chunk(sb, 0, Ahi, Alo, Bhi, Blo, m0, n0, 0, tid);

    for (int kc = 0; kc < 32; kc++) {
        CP_WAIT0();
        __syncthreads();
        if (kc + 1 < 32)
            gemm_issue_chunk(sb, (kc + 1) & 1, Ahi, Alo, Bhi, Blo, m0, n0, (kc + 1) * 32, tid);

        uint32_t st  = sb + (kc & 1) * G_STAGE;
        uint32_t bAh = st, bAl = st + 10240, bBh = st + 20480, bBl = st + 30720;
#pragma unroll
        for (int s = 0; s < 2; s++) {
            int k0 = s * 16;
            uint32_t ah[4][4], al[4][4], bh[2][4], bl[2][4];
#pragma unroll
            for (int mi = 0; mi < 4; mi++) {
                int row = wm * 64 + mi * 16 + (l & 15);
                int col = k0 + ((l >> 4) << 3);
                uint32_t off = (uint32_t)(row * 40 + col) * 2;
                ldsm4(ah[mi], bAh + off);
                ldsm4(al[mi], bAl + off);
            }
#pragma unroll
            for (int np = 0; np < 2; np++) {
                int row = wn * 32 + np * 16 + (l & 7) + ((l >> 4) << 3);
                int col = k0 + (((l >> 3) & 1) << 3);
                uint32_t off = (uint32_t)(row * 40 + col) * 2;
                ldsm4(bh[np], bBh + off);
                ldsm4(bl[np], bBl + off);
            }
#pragma unroll
            for (int mi = 0; mi < 4; mi++)
#pragma unroll
                for (int ni = 0; ni < 4; ni++)
                    mma_bf16(acc[mi][ni], ah[mi], &bh[ni >> 1][(ni & 1) * 2]);
#pragma unroll
            for (int mi = 0; mi < 4; mi++)
#pragma unroll
                for (int ni = 0; ni < 4; ni++)
                    mma_bf16(acc[mi][ni], ah[mi], &bl[ni >> 1][(ni & 1) * 2]);
#pragma unroll
            for (int mi = 0; mi < 4; mi++)
#pragma unroll
                for (int ni = 0; ni < 4; ni++)
                    mma_bf16(acc[mi][ni], al[mi], &bh[ni >> 1][(ni & 1) * 2]);
        }
    }
    // epilogue
#pragma unroll
    for (int mi = 0; mi < 4; mi++) {
        int row0 = m0 + wm * 64 + mi * 16 + (l >> 2);
#pragma unroll
        for (int ni = 0; ni < 4; ni++) {
            int col = n0 + wn * 32 + ni * 8 + ((l & 3) << 1);
            float b0 = bias[col], b1 = bias[col + 1];
            float v00 = (acc[mi][ni][0] + b0) * scale;
            float v01 = (acc[mi][ni][1] + b1) * scale;
            float v10 = (acc[mi][ni][2] + b0) * scale;
            float v11 = (acc[mi][ni][3] + b1) * scale;
            size_t o0 = (size_t)row0 * D_ + col;
            size_t o1 = o0 + (size_t)8 * D_;
            if (mode == 0) {
                *(float2*)(Cf + o0) = make_float2(v00, v01);
                *(float2*)(Cf + o1) = make_float2(v10, v11);
            } else if (mode == 1) {
                __half2 h0, h1;
                h0.x = __float2half_rn(v00); h0.y = __float2half_rn(v01);
                h1.x = __float2half_rn(v10); h1.y = __float2half_rn(v11);
                *(__half2*)(H0 + o0) = h0;
                *(__half2*)(H0 + o1) = h1;
            } else {
                __half2 h0, h1, l0p, l1p;
                h0.x = __float2half_rn(v00); h0.y = __float2half_rn(v01);
                h1.x = __float2half_rn(v10); h1.y = __float2half_rn(v11);
                l0p.x = __float2half_rn(v00 - __half2float(h0.x));
                l0p.y = __float2half_rn(v01 - __half2float(h0.y));
                l1p.x = __float2half_rn(v10 - __half2float(h1.x));
                l1p.y = __float2half_rn(v11 - __half2float(h1.y));
                *(__half2*)(H0 + o0) = h0;
                *(__half2*)(H0 + o1) = h1;
                *(__half2*)(H1 + o0) = l0p;
                *(__half2*)(H1 + o1) = l1p;
            }
        }
    }
}

__global__ __launch_bounds__(256, 2) void gemm_qkv(
    const float* __restrict__ bq, const float* __restrict__ bk, const float* __restrict__ bv)
{
    extern __shared__ char smem[];
    int z = blockIdx.z;
    const size_t WSZ = (size_t)D_ * D_;
    const __nv_bfloat16* Bh = g_wthi + (size_t)z * WSZ;
    const __nv_bfloat16* Bl = g_wtlo + (size_t)z * WSZ;
    const float* bias = (z == 0) ? bq : (z == 1) ? bk : bv;
    __half* H0 = (z == 0) ? g_qf : (z == 1) ? g_kf : g_vh;
    __half* H1 = g_vl;
    int mode = (z == 2) ? 2 : 1;
    float scale = (z == 0) ? 0.125f : 1.0f;
    gemm_body(g_xhi, g_xlo, Bh, Bl, bias, scale, mode, nullptr, H0, H1, smem);
}

__global__ __launch_bounds__(256, 2) void gemm_o(const float* __restrict__ bo, float* __restrict__ out)
{
    extern __shared__ char smem[];
    const size_t WSZ = (size_t)D_ * D_;
    gemm_body(g_aohi, g_aolo, g_wthi + 3 * WSZ, g_wtlo + 3 * WSZ, bo, 1.0f, 0, out, nullptr, nullptr, smem);
}

// ---------------- fp16 HMMA flash attention (cp.async 2-stage) ----------------
// Stage (bytes): K 0..9216, Vh 9216..18432, Vl 18432..27648, E 27648, R 27904; stride 28160.
static constexpr int A_STAGE = 28160;
static constexpr int A_SMEM  = 2 * A_STAGE;

__device__ __forceinline__ void attn_issue_tile(uint32_t sb, int stage, int b, int h, int kt, int tid) {
    uint32_t st = sb + stage * A_STAGE;
#pragma unroll
    for (int j = 0; j < 12; j++) {
        int a = j >> 2;
        int rem = tid + (j & 3) * 128;
        int r = rem >> 3, c = rem & 7;
        const __half* base = (a == 0) ? g_kf : (a == 1) ? g_vh : g_vl;
        uint32_t dst = st + (uint32_t)a * 9216u + (uint32_t)(r * 144 + c * 16);
        const __half* src = base + (size_t)(b * S_ + kt + r) * D_ + h * HD_ + c * 8;
        CP16(dst, src);
    }
    if (tid < 16)      CP16(st + 27648u + tid * 16, &g_E[b * S_ + kt + tid * 4]);
    else if (tid < 32) CP16(st + 27904u + (tid - 16) * 16, &g_R[b * S_ + kt + (tid - 16) * 4]);
    CP_COMMIT();
}

__global__ __launch_bounds__(128) void attn_mma() {
    extern __shared__ char smem[];
    uint32_t sb = smem_u32(smem);
    int tid = threadIdx.x, l = tid & 31, wid = tid >> 5;
    int h = blockIdx.y, b = blockIdx.z;
    int q0 = blockIdx.x * 64;

    // ---- stage q (fp16 single) through stage-0 K region, pull frags ----
    __half* qstage = (__half*)smem;
    uint32_t qh[4][4];
#pragma unroll
    for (int t = 0; t < 4; t++) {
        int i = tid + t * 128;
        int r = i >> 3, c8 = (i & 7) << 3;
        *(uint4*)(qstage + r * 72 + c8) =
            *(const uint4*)(g_qf + (size_t)(b * S_ + q0 + r) * D_ + h * HD_ + c8);
    }
    __syncthreads();
#pragma unroll
    for (int ks = 0; ks < 4; ks++) {
        int row = wid * 16 + (l & 15);
        int col = ks * 16 + ((l >> 4) << 3);
        ldsm4(qh[ks], sb + (uint32_t)(row * 72 + col) * 2);
    }
    __syncthreads();

    int r0 = wid * 16 + (l >> 2), r1 = r0 + 8;
    float Ei0 = g_E[b * S_ + q0 + r0], Ri0 = g_R[b * S_ + q0 + r0];
    float Ei1 = g_E[b * S_ + q0 + r1], Ri1 = g_R[b * S_ + q0 + r1];

    float Oa[8][4];
#pragma unroll
    for (int f = 0; f < 8; f++)
#pragma unroll
        for (int c = 0; c < 4; c++) Oa[f][c] = 0.f;
    float m0v = -1e30f, m1v = -1e30f, l0v = 0.f, l1v = 0.f;

    attn_issue_tile(sb, 0, b, h, 0, tid);

    for (int t = 0; t < S_ / 64; t++) {
        CP_WAIT0();
        __syncthreads();
        if (t + 1 < S_ / 64)
            attn_issue_tile(sb, (t + 1) & 1, b, h, (t + 1) * 64, tid);

        uint32_t st  = sb + (t & 1) * A_STAGE;
        uint32_t bK = st, bVh = st + 9216, bVl = st + 18432;
        const float* sE = (const float*)(smem + (t & 1) * A_STAGE + 27648);
        const float* sR = (const float*)(smem + (t & 1) * A_STAGE + 27904);

        // scores: S = q . K   (single fp16 stream)
        float Sa[8][4];
#pragma unroll
        for (int f = 0; f < 8; f++)
#pragma unroll
            for (int c = 0; c < 4; c++) Sa[f][c] = 0.f;
#pragma unroll
        for (int ks = 0; ks < 4; ks++) {
            uint32_t kh[4][4];
#pragma unroll
            for (int g2 = 0; g2 < 4; g2++) {
                int row = g2 * 16 + (l & 7) + ((l >> 4) << 3);
                int col = ks * 16 + (((l >> 3) & 1) << 3);
                ldsm4(kh[g2], bK + (uint32_t)(row * 72 + col) * 2);
            }
#pragma unroll
            for (int f = 0; f < 8; f++)
                mma_f16(Sa[f], qh[ks], &kh[f >> 1][(f & 1) * 2]);
        }

        // decay + tile max
        int c0 = (l & 3) << 1;
        float mx0 = -1e30f, mx1 = -1e30f;
#pragma unroll
        for (int f = 0; f < 8; f++) {
            int j = f * 8 + c0;
            float Ej0 = sE[j], Rj0 = sR[j], Ej1 = sE[j + 1], Rj1 = sR[j + 1];
            Sa[f][0] *= fminf(Ei0 * Rj0, Ej0 * Ri0);
            Sa[f][1] *= fminf(Ei0 * Rj1, Ej1 * Ri0);
            Sa[f][2] *= fminf(Ei1 * Rj0, Ej0 * Ri1);
            Sa[f][3] *= fminf(Ei1 * Rj1, Ej1 * Ri1);
            mx0 = fmaxf(mx0, fmaxf(Sa[f][0], Sa[f][1]));
            mx1 = fmaxf(mx1, fmaxf(Sa[f][2], Sa[f][3]));
        }
        mx0 = fmaxf(mx0, __shfl_xor_sync(0xffffffffu, mx0, 1));
        mx0 = fmaxf(mx0, __shfl_xor_sync(0xffffffffu, mx0, 2));
        mx1 = fmaxf(mx1, __shfl_xor_sync(0xffffffffu, mx1, 1));
        mx1 = fmaxf(mx1, __shfl_xor_sync(0xffffffffu, mx1, 2));

        float mn0 = fmaxf(m0v, mx0), mn1 = fmaxf(m1v, mx1);
        float sc0 = fast_exp(m0v - mn0), sc1 = fast_exp(m1v - mn1);
        m0v = mn0; m1v = mn1;
        l0v *= sc0; l1v *= sc1;
#pragma unroll
        for (int f = 0; f < 8; f++) {
            Oa[f][0] *= sc0; Oa[f][1] *= sc0;
            Oa[f][2] *= sc1; Oa[f][3] *= sc1;
        }

        // p = exp(s - m) -> fp16 frags; l accumulated from ROUNDED p (num/denom consistent)
        uint32_t Ph[8][2];
        float rs0 = 0.f, rs1 = 0.f;
#pragma unroll
        for (int f = 0; f < 8; f++) {
            float p00 = fast_exp(Sa[f][0] - mn0);
            float p01 = fast_exp(Sa[f][1] - mn0);
            float p10 = fast_exp(Sa[f][2] - mn1);
            float p11 = fast_exp(Sa[f][3] - mn1);
            uint32_t h0 = pack2h(p00, p01);
            uint32_t h1 = pack2h(p10, p11);
            Ph[f][0] = h0; Ph[f][1] = h1;
            float2 f0 = __half22float2(*reinterpret_cast<__half2*>(&h0));
            float2 f1 = __half22float2(*reinterpret_cast<__half2*>(&h1));
            rs0 += f0.x + f0.y;
            rs1 += f1.x + f1.y;
        }
        rs0 += __shfl_xor_sync(0xffffffffu, rs0, 1);
        rs0 += __shfl_xor_sync(0xffffffffu, rs0, 2);
        rs1 += __shfl_xor_sync(0xffffffffu, rs1, 1);
        rs1 += __shfl_xor_sync(0xffffffffu, rs1, 2);
        l0v += rs0; l1v += rs1;

        // O += P.Vhi + P.Vlo   (2 fp16 streams)
#pragma unroll
        for (int ks = 0; ks < 4; ks++) {
            uint32_t pah[4] = {Ph[2*ks][0], Ph[2*ks][1], Ph[2*ks+1][0], Ph[2*ks+1][1]};
            uint32_t vh[4][4], vl[4][4];
#pragma unroll
            for (int db = 0; db < 4; db++) {
                int row = ks * 16 + (l & 7) + (((l >> 3) & 1) << 3);
                int col = db * 16 + ((l >> 4) << 3);
                uint32_t off = (uint32_t)(row * 72 + col) * 2;
                ldsm4t(vh[db], bVh + off);
                ldsm4t(vl[db], bVl + off);
            }
#pragma unroll
            for (int db = 0; db < 4; db++) {
                mma_f16(Oa[2*db],   pah, &vh[db][0]);
                mma_f16(Oa[2*db+1], pah, &vh[db][2]);
            }
#pragma unroll
            for (int db = 0; db < 4; db++) {
                mma_f16(Oa[2*db],   pah, &vl[db][0]);
                mma_f16(Oa[2*db+1], pah, &vl[db][2]);
            }
        }
    }

    // normalize + split-write ao (bf16 hi/lo for the 3-stream O-projection)
    float inv0 = 1.0f / l0v, inv1 = 1.0f / l1v;
    int c0 = (l & 3) << 1;
    size_t ro0 = (size_t)(b * S_ + q0 + r0) * D_ + h * HD_;
    size_t ro1 = (size_t)(b * S_ + q0 + r1) * D_ + h * HD_;
#pragma unroll
    for (int f = 0; f < 8; f++) {
        int d = f * 8 + c0;
        float v00 = Oa[f][0] * inv0, v01 = Oa[f][1] * inv0;
        float v10 = Oa[f][2] * inv1, v11 = Oa[f][3] * inv1;
        __nv_bfloat162 h0, h1, lo0, lo1;
        h0.x = __float2bfloat16_rn(v00); h0.y = __float2bfloat16_rn(v01);
        h1.x = __float2bfloat16_rn(v10); h1.y = __float2bfloat16_rn(v11);
        lo0.x = __float2bfloat16_rn(v00 - __bfloat162float(h0.x));
        lo0.y = __float2bfloat16_rn(v01 - __bfloat162float(h0.y));
        lo1.x = __float2bfloat16_rn(v10 - __bfloat162float(h1.x));
        lo1.y = __float2bfloat16_rn(v11 - __bfloat162float(h1.y));
        *(__nv_bfloat162*)(g_aohi + ro0 + d) = h0;
        *(__nv_bfloat162*)(g_aohi + ro1 + d) = h1;
        *(__nv_bfloat162*)(g_aolo + ro0 + d) = lo0;
        *(__nv_bfloat162*)(g_aolo + ro1 + d) = lo1;
    }
}

// ---------------- launch ----------------
extern "C" void kernel_launch(void* const* d_in, const int* in_sizes, int n_in,
                              void* d_out, int out_size) {
    const float* x  = (const float*)d_in[0];
    const float* ts = (const float*)d_in[1];
    const float* Wq = (const float*)d_in[2];
    const float* bq = (const float*)d_in[3];
    const float* Wk = (const float*)d_in[4];
    const float* bk = (const float*)d_in[5];
    const float* Wv = (const float*)d_in[6];
    const float* bv = (const float*)d_in[7];
    const float* Wo = (const float*)d_in[8];
    const float* bo = (const float*)d_in[9];
    const float* td = (const float*)d_in[10];
    float* out = (float*)d_out;

    __nv_bfloat16 *xhi, *xlo, *wthi, *wtlo;
    cudaGetSymbolAddress((void**)&xhi,  g_xhi);
    cudaGetSymbolAddress((void**)&xlo,  g_xlo);
    cudaGetSymbolAddress((void**)&wthi, g_wthi);
    cudaGetSymbolAddress((void**)&wtlo, g_wtlo);

    static int attr_done = 0;
    if (!attr_done) {
        cudaFuncSetAttribute(gemm_qkv, cudaFuncAttributeMaxDynamicSharedMemorySize, G_SMEM);
        cudaFuncSetAttribute(gemm_o,   cudaFuncAttributeMaxDynamicSharedMemorySize, G_SMEM);
        cudaFuncSetAttribute(attn_mma, cudaFuncAttributeMaxDynamicSharedMemorySize, A_SMEM);
        attr_done = 1;
    }

    prep_kernel<<<M_ / 256, 256>>>(ts, td);
    split_kernel<<<(M_ * D_) / 256, 256>>>(x, xhi, xlo);
    transpose_split_all<<<dim3(D_ / 32, D_ / 32, 4), dim3(32, 8)>>>(Wq, Wk, Wv, Wo, wthi, wtlo);

    gemm_qkv<<<dim3(D_ / 128, M_ / 128, 3), 256, G_SMEM>>>(bq, bk, bv);
    attn_mma<<<dim3(S_ / 64, H_, B_), 128, A_SMEM>>>();
    gemm_o<<<dim3(D_ / 128, M_ / 128), 256, G_SMEM>>>(bo, out);
}

// round 15
// speedup vs baseline: 1.4662x; 1.1473x over previous
#include <cuda_runtime.h>
#include <cuda_bf16.h>
#include <cuda_fp16.h>
#include <math.h>
#include <cstdint>

#define B_  2
#define S_  2048
#define D_  1024
#define H_  16
#define HD_ 64
#define M_  (B_*S_)

// ---------------- scratch (no allocs allowed) ----------------
__device__ float g_E[M_], g_R[M_];
__device__ __half        g_xf  [M_*D_];                       // x, fp16 single
__device__ __half        g_qf  [M_*D_];                       // q, fp16 single (1/8 folded)
__device__ __half        g_kf  [M_*D_];                       // k, fp16 single
__device__ __half        g_vh  [M_*D_], g_vl [M_*D_];         // v, fp16 hi/lo split
__device__ __nv_bfloat16 g_aohi[M_*D_], g_aolo[M_*D_];
__device__ __half        g_wfh [3u*D_*D_], g_wfl [3u*D_*D_];  // Wq/Wk/Wv^T fp16 hi/lo
__device__ __nv_bfloat16 g_wthi[D_*D_],    g_wtlo[D_*D_];     // Wo^T bf16 hi/lo

// ================= helpers =================
__device__ __forceinline__ uint32_t smem_u32(const void* p) {
    uint32_t a;
    asm("{ .reg .u64 t; cvta.to.shared.u64 t, %1; cvt.u32.u64 %0, t; }" : "=r"(a) : "l"(p));
    return a;
}
__device__ __forceinline__ void ldsm4(uint32_t* r, uint32_t a) {
    asm volatile("ldmatrix.sync.aligned.m8n8.x4.shared.b16 {%0,%1,%2,%3}, [%4];"
        : "=r"(r[0]), "=r"(r[1]), "=r"(r[2]), "=r"(r[3]) : "r"(a));
}
__device__ __forceinline__ void ldsm4t(uint32_t* r, uint32_t a) {
    asm volatile("ldmatrix.sync.aligned.m8n8.x4.trans.shared.b16 {%0,%1,%2,%3}, [%4];"
        : "=r"(r[0]), "=r"(r[1]), "=r"(r[2]), "=r"(r[3]) : "r"(a));
}
__device__ __forceinline__ void mma_bf16(float* c, const uint32_t* a, const uint32_t* b) {
    asm volatile("mma.sync.aligned.m16n8k16.row.col.f32.bf16.bf16.f32 "
        "{%0,%1,%2,%3}, {%4,%5,%6,%7}, {%8,%9}, {%0,%1,%2,%3};"
        : "+f"(c[0]), "+f"(c[1]), "+f"(c[2]), "+f"(c[3])
        : "r"(a[0]), "r"(a[1]), "r"(a[2]), "r"(a[3]), "r"(b[0]), "r"(b[1]));
}
__device__ __forceinline__ void mma_f16(float* c, const uint32_t* a, const uint32_t* b) {
    asm volatile("mma.sync.aligned.m16n8k16.row.col.f32.f16.f16.f32 "
        "{%0,%1,%2,%3}, {%4,%5,%6,%7}, {%8,%9}, {%0,%1,%2,%3};"
        : "+f"(c[0]), "+f"(c[1]), "+f"(c[2]), "+f"(c[3])
        : "r"(a[0]), "r"(a[1]), "r"(a[2]), "r"(a[3]), "r"(b[0]), "r"(b[1]));
}
__device__ __forceinline__ uint32_t pack2h(float lo, float hi) {
    uint32_t r;
    asm("cvt.rn.f16x2.f32 %0, %1, %2;" : "=r"(r) : "f"(hi), "f"(lo));
    return r;
}

#define CP16(dst, src) asm volatile("cp.async.cg.shared.global [%0], [%1], 16;" :: "r"(dst), "l"(src))
#define CP_COMMIT()    asm volatile("cp.async.commit_group;" ::: "memory")
#define CP_WAIT0()     asm volatile("cp.async.wait_group 0;" ::: "memory")

// FFMA-only exp (x <= 0 expected)
__device__ __forceinline__ float fast_exp(float x) {
    x = fmaxf(x, -80.0f);
    float t = x * 1.4426950408889634f;
    float z = t + 12582912.0f;
    int  ni = __float_as_int(z) - 0x4B400000;
    float n = z - 12582912.0f;
    float g = fmaf(n, -0.6931471805599453f, x);
    float p = 1.3888889e-3f;
    p = fmaf(p, g, 8.3333333e-3f);
    p = fmaf(p, g, 4.1666667e-2f);
    p = fmaf(p, g, 1.6666667e-1f);
    p = fmaf(p, g, 0.5f);
    p = fmaf(p, g, 1.0f);
    p = fmaf(p, g, 1.0f);
    return p * __int_as_float((ni + 127) << 23);
}

// ---------------- small prep kernels ----------------
__global__ void prep_kernel(const float* __restrict__ ts, const float* __restrict__ td) {
    int i = blockIdx.x * 256 + threadIdx.x;
    if (i < M_) {
        float e = expf(td[0] * ts[i]);
        g_E[i] = e;
        g_R[i] = 1.0f / e;
    }
}
__global__ __launch_bounds__(256) void xcvt_kernel(const float* __restrict__ src) {
    int i = blockIdx.x * 256 + threadIdx.x;
    g_xf[i] = __float2half_rn(src[i]);
}
// transpose: z<3 -> fp16 hi/lo (Wq/Wk/Wv), z==3 -> bf16 hi/lo (Wo)
__global__ __launch_bounds__(256) void transpose_split_all(
    const float* __restrict__ W0, const float* __restrict__ W1,
    const float* __restrict__ W2, const float* __restrict__ W3)
{
    __shared__ float tile[32][33];
    int z = blockIdx.z;
    const float* W = (z == 0) ? W0 : (z == 1) ? W1 : (z == 2) ? W2 : W3;
    int tx = threadIdx.x, ty = threadIdx.y;
    int n0 = blockIdx.x * 32, k0 = blockIdx.y * 32;
#pragma unroll
    for (int j = 0; j < 32; j += 8)
        tile[ty + j][tx] = W[(size_t)(k0 + ty + j) * D_ + n0 + tx];
    __syncthreads();
    if (z < 3) {
        size_t zoff = (size_t)z * D_ * D_;
#pragma unroll
        for (int j = 0; j < 32; j += 8) {
            float f = tile[tx][ty + j];
            __half h = __float2half_rn(f);
            size_t o = zoff + (size_t)(n0 + ty + j) * D_ + k0 + tx;
            g_wfh[o] = h;
            g_wfl[o] = __float2half_rn(f - __half2float(h));
        }
    } else {
#pragma unroll
        for (int j = 0; j < 32; j += 8) {
            float f = tile[tx][ty + j];
            __nv_bfloat16 h = __float2bfloat16_rn(f);
            size_t o = (size_t)(n0 + ty + j) * D_ + k0 + tx;
            g_wthi[o] = h;
            g_wtlo[o] = __float2bfloat16_rn(f - __bfloat162float(h));
        }
    }
}

// ---------------- QKV: 2-stream fp16 GEMM (x single, W hi/lo), cp.async 2-stage ----------------
// Stage (bytes): A 0..10240, Bh 10240..20480, Bl 20480..30720; stride 30720.
static constexpr int G2_STAGE = 30720;
static constexpr int G2_SMEM  = 2 * G2_STAGE;

__device__ __forceinline__ void qkv_issue_chunk(
    uint32_t sb, int stage, const __half* Bh, const __half* Bl,
    int m0, int n0, int k0, int tid)
{
    uint32_t st = sb + stage * G2_STAGE;
#pragma unroll
    for (int j = 0; j < 6; j++) {
        int a = j >> 1;
        int rem = tid + (j & 1) * 256;
        int r = rem >> 2, c4 = rem & 3;
        const __half* base = (a == 0) ? g_xf : (a == 1) ? Bh : Bl;
        int rowbase = (a == 0) ? m0 : n0;
        uint32_t dst = st + (uint32_t)a * 10240u + (uint32_t)(r * 80 + c4 * 16);
        const __half* src = base + (size_t)(rowbase + r) * D_ + k0 + c4 * 8;
        CP16(dst, src);
    }
    CP_COMMIT();
}

__global__ __launch_bounds__(256, 2) void gemm_qkv(
    const float* __restrict__ bq, const float* __restrict__ bk, const float* __restrict__ bv)
{
    extern __shared__ char smem[];
    uint32_t sb = smem_u32(smem);
    int z = blockIdx.z;
    const size_t WSZ = (size_t)D_ * D_;
    const __half* Bh = g_wfh + (size_t)z * WSZ;
    const __half* Bl = g_wfl + (size_t)z * WSZ;
    const float* bias = (z == 0) ? bq : (z == 1) ? bk : bv;
    float scale = (z == 0) ? 0.125f : 1.0f;

    int tid = threadIdx.x, l = tid & 31, wid = tid >> 5;
    int wm = wid >> 2, wn = wid & 3;
    int m0 = blockIdx.y * 128, n0 = blockIdx.x * 128;

    float acc[4][4][4];
#pragma unroll
    for (int a = 0; a < 4; a++)
#pragma unroll
        for (int b2 = 0; b2 < 4; b2++)
#pragma unroll
            for (int c = 0; c < 4; c++) acc[a][b2][c] = 0.f;

    qkv_issue_chunk(sb, 0, Bh, Bl, m0, n0, 0, tid);

    for (int kc = 0; kc < 32; kc++) {
        CP_WAIT0();
        __syncthreads();
        if (kc + 1 < 32)
            qkv_issue_chunk(sb, (kc + 1) & 1, Bh, Bl, m0, n0, (kc + 1) * 32, tid);

        uint32_t st = sb + (kc & 1) * G2_STAGE;
        uint32_t bA = st, bBh = st + 10240, bBl = st + 20480;
#pragma unroll
        for (int s = 0; s < 2; s++) {
            int k0 = s * 16;
            uint32_t af[4][4], bh[2][4], bl[2][4];
#pragma unroll
            for (int mi = 0; mi < 4; mi++) {
                int row = wm * 64 + mi * 16 + (l & 15);
                int col = k0 + ((l >> 4) << 3);
                ldsm4(af[mi], bA + (uint32_t)(row * 40 + col) * 2);
            }
#pragma unroll
            for (int np = 0; np < 2; np++) {
                int row = wn * 32 + np * 16 + (l & 7) + ((l >> 4) << 3);
                int col = k0 + (((l >> 3) & 1) << 3);
                uint32_t off = (uint32_t)(row * 40 + col) * 2;
                ldsm4(bh[np], bBh + off);
                ldsm4(bl[np], bBl + off);
            }
#pragma unroll
            for (int mi = 0; mi < 4; mi++)
#pragma unroll
                for (int ni = 0; ni < 4; ni++)
                    mma_f16(acc[mi][ni], af[mi], &bh[ni >> 1][(ni & 1) * 2]);
#pragma unroll
            for (int mi = 0; mi < 4; mi++)
#pragma unroll
                for (int ni = 0; ni < 4; ni++)
                    mma_f16(acc[mi][ni], af[mi], &bl[ni >> 1][(ni & 1) * 2]);
        }
    }
    // epilogue: z<2 -> fp16 single (q/k), z==2 -> fp16 split (v)
#pragma unroll
    for (int mi = 0; mi < 4; mi++) {
        int row0 = m0 + wm * 64 + mi * 16 + (l >> 2);
#pragma unroll
        for (int ni = 0; ni < 4; ni++) {
            int col = n0 + wn * 32 + ni * 8 + ((l & 3) << 1);
            float b0 = bias[col], b1 = bias[col + 1];
            float v00 = (acc[mi][ni][0] + b0) * scale;
            float v01 = (acc[mi][ni][1] + b1) * scale;
            float v10 = (acc[mi][ni][2] + b0) * scale;
            float v11 = (acc[mi][ni][3] + b1) * scale;
            size_t o0 = (size_t)row0 * D_ + col;
            size_t o1 = o0 + (size_t)8 * D_;
            __half2 h0, h1;
            h0.x = __float2half_rn(v00); h0.y = __float2half_rn(v01);
            h1.x = __float2half_rn(v10); h1.y = __float2half_rn(v11);
            if (z == 0) {
                *(__half2*)(g_qf + o0) = h0;
                *(__half2*)(g_qf + o1) = h1;
            } else if (z == 1) {
                *(__half2*)(g_kf + o0) = h0;
                *(__half2*)(g_kf + o1) = h1;
            } else {
                *(__half2*)(g_vh + o0) = h0;
                *(__half2*)(g_vh + o1) = h1;
                __half2 l0p, l1p;
                l0p.x = __float2half_rn(v00 - __half2float(h0.x));
                l0p.y = __float2half_rn(v01 - __half2float(h0.y));
                l1p.x = __float2half_rn(v10 - __half2float(h1.x));
                l1p.y = __float2half_rn(v11 - __half2float(h1.y));
                *(__half2*)(g_vl + o0) = l0p;
                *(__half2*)(g_vl + o1) = l1p;
            }
        }
    }
}

// ---------------- O-proj: 3-stream bf16 GEMM (unchanged math), cp.async 2-stage ----------------
static constexpr int G_STAGE = 40960;
static constexpr int G_SMEM  = 2 * G_STAGE;

__device__ __forceinline__ void o_issue_chunk(uint32_t sb, int stage, int m0, int n0, int k0, int tid) {
    uint32_t st = sb + stage * G_STAGE;
#pragma unroll
    for (int j = 0; j < 8; j++) {
        int rem = tid + (j & 1) * 256;
        int r = rem >> 2, c4 = rem & 3;
        const __nv_bfloat16* base = (j < 2) ? g_aohi : (j < 4) ? g_aolo : (j < 6) ? g_wthi : g_wtlo;
        int rowbase = (j < 4) ? m0 : n0;
        uint32_t dst = st + (uint32_t)(j >> 1) * 10240u + (uint32_t)(r * 80 + c4 * 16);
        const __nv_bfloat16* src = base + (size_t)(rowbase + r) * D_ + k0 + c4 * 8;
        CP16(dst, src);
    }
    CP_COMMIT();
}

__global__ __launch_bounds__(256, 2) void gemm_o(const float* __restrict__ bo, float* __restrict__ out)
{
    extern __shared__ char smem[];
    uint32_t sb = smem_u32(smem);
    int tid = threadIdx.x, l = tid & 31, wid = tid >> 5;
    int wm = wid >> 2, wn = wid & 3;
    int m0 = blockIdx.y * 128, n0 = blockIdx.x * 128;

    float acc[4][4][4];
#pragma unroll
    for (int a = 0; a < 4; a++)
#pragma unroll
        for (int b2 = 0; b2 < 4; b2++)
#pragma unroll
            for (int c = 0; c < 4; c++) acc[a][b2][c] = 0.f;

    o_issue_chunk(sb, 0, m0, n0, 0, tid);

    for (int kc = 0; kc < 32; kc++) {
        CP_WAIT0();
        __syncthreads();
        if (kc + 1 < 32)
            o_issue_chunk(sb, (kc + 1) & 1, m0, n0, (kc + 1) * 32, tid);

        uint32_t st  = sb + (kc & 1) * G_STAGE;
        uint32_t bAh = st, bAl = st + 10240, bBh = st + 20480, bBl = st + 30720;
#pragma unroll
        for (int s = 0; s < 2; s++) {
            int k0 = s * 16;
            uint32_t ah[4][4], al[4][4], bh[2][4], bl[2][4];
#pragma unroll
            for (int mi = 0; mi < 4; mi++) {
                int row = wm * 64 + mi * 16 + (l & 15);
                int col = k0 + ((l >> 4) << 3);
                uint32_t off = (uint32_t)(row * 40 + col) * 2;
                ldsm4(ah[mi], bAh + off);
                ldsm4(al[mi], bAl + off);
            }
#pragma unroll
            for (int np = 0; np < 2; np++) {
                int row = wn * 32 + np * 16 + (l & 7) + ((l >> 4) << 3);
                int col = k0 + (((l >> 3) & 1) << 3);
                uint32_t off = (uint32_t)(row * 40 + col) * 2;
                ldsm4(bh[np], bBh + off);
                ldsm4(bl[np], bBl + off);
            }
#pragma unroll
            for (int mi = 0; mi < 4; mi++)
#pragma unroll
                for (int ni = 0; ni < 4; ni++)
                    mma_bf16(acc[mi][ni], ah[mi], &bh[ni >> 1][(ni & 1) * 2]);
#pragma unroll
            for (int mi = 0; mi < 4; mi++)
#pragma unroll
                for (int ni = 0; ni < 4; ni++)
                    mma_bf16(acc[mi][ni], ah[mi], &bl[ni >> 1][(ni & 1) * 2]);
#pragma unroll
            for (int mi = 0; mi < 4; mi++)
#pragma unroll
                for (int ni = 0; ni < 4; ni++)
                    mma_bf16(acc[mi][ni], al[mi], &bh[ni >> 1][(ni & 1) * 2]);
        }
    }
#pragma unroll
    for (int mi = 0; mi < 4; mi++) {
        int row0 = m0 + wm * 64 + mi * 16 + (l >> 2);
#pragma unroll
        for (int ni = 0; ni < 4; ni++) {
            int col = n0 + wn * 32 + ni * 8 + ((l & 3) << 1);
            float b0 = bo[col], b1 = bo[col + 1];
            size_t o0 = (size_t)row0 * D_ + col;
            size_t o1 = o0 + (size_t)8 * D_;
            *(float2*)(out + o0) = make_float2(acc[mi][ni][0] + b0, acc[mi][ni][1] + b1);
            *(float2*)(out + o1) = make_float2(acc[mi][ni][2] + b0, acc[mi][ni][3] + b1);
        }
    }
}

// ---------------- fp16 HMMA flash attention (cp.async 2-stage) ----------------
static constexpr int A_STAGE = 28160;
static constexpr int A_SMEM  = 2 * A_STAGE;

__device__ __forceinline__ void attn_issue_tile(uint32_t sb, int stage, int b, int h, int kt, int tid) {
    uint32_t st = sb + stage * A_STAGE;
#pragma unroll
    for (int j = 0; j < 12; j++) {
        int a = j >> 2;
        int rem = tid + (j & 3) * 128;
        int r = rem >> 3, c = rem & 7;
        const __half* base = (a == 0) ? g_kf : (a == 1) ? g_vh : g_vl;
        uint32_t dst = st + (uint32_t)a * 9216u + (uint32_t)(r * 144 + c * 16);
        const __half* src = base + (size_t)(b * S_ + kt + r) * D_ + h * HD_ + c * 8;
        CP16(dst, src);
    }
    if (tid < 16)      CP16(st + 27648u + tid * 16, &g_E[b * S_ + kt + tid * 4]);
    else if (tid < 32) CP16(st + 27904u + (tid - 16) * 16, &g_R[b * S_ + kt + (tid - 16) * 4]);
    CP_COMMIT();
}

__global__ __launch_bounds__(128) void attn_mma() {
    extern __shared__ char smem[];
    uint32_t sb = smem_u32(smem);
    int tid = threadIdx.x, l = tid & 31, wid = tid >> 5;
    int h = blockIdx.y, b = blockIdx.z;
    int q0 = blockIdx.x * 64;

    __half* qstage = (__half*)smem;
    uint32_t qh[4][4];
#pragma unroll
    for (int t = 0; t < 4; t++) {
        int i = tid + t * 128;
        int r = i >> 3, c8 = (i & 7) << 3;
        *(uint4*)(qstage + r * 72 + c8) =
            *(const uint4*)(g_qf + (size_t)(b * S_ + q0 + r) * D_ + h * HD_ + c8);
    }
    __syncthreads();
#pragma unroll
    for (int ks = 0; ks < 4; ks++) {
        int row = wid * 16 + (l & 15);
        int col = ks * 16 + ((l >> 4) << 3);
        ldsm4(qh[ks], sb + (uint32_t)(row * 72 + col) * 2);
    }
    __syncthreads();

    int r0 = wid * 16 + (l >> 2), r1 = r0 + 8;
    float Ei0 = g_E[b * S_ + q0 + r0], Ri0 = g_R[b * S_ + q0 + r0];
    float Ei1 = g_E[b * S_ + q0 + r1], Ri1 = g_R[b * S_ + q0 + r1];

    float Oa[8][4];
#pragma unroll
    for (int f = 0; f < 8; f++)
#pragma unroll
        for (int c = 0; c < 4; c++) Oa[f][c] = 0.f;
    float m0v = -1e30f, m1v = -1e30f, l0v = 0.f, l1v = 0.f;

    attn_issue_tile(sb, 0, b, h, 0, tid);

    for (int t = 0; t < S_ / 64; t++) {
        CP_WAIT0();
        __syncthreads();
        if (t + 1 < S_ / 64)
            attn_issue_tile(sb, (t + 1) & 1, b, h, (t + 1) * 64, tid);

        uint32_t st  = sb + (t & 1) * A_STAGE;
        uint32_t bK = st, bVh = st + 9216, bVl = st + 18432;
        const float* sE = (const float*)(smem + (t & 1) * A_STAGE + 27648);
        const float* sR = (const float*)(smem + (t & 1) * A_STAGE + 27904);

        float Sa[8][4];
#pragma unroll
        for (int f = 0; f < 8; f++)
#pragma unroll
            for (int c = 0; c < 4; c++) Sa[f][c] = 0.f;
#pragma unroll
        for (int ks = 0; ks < 4; ks++) {
            uint32_t kh[4][4];
#pragma unroll
            for (int g2 = 0; g2 < 4; g2++) {
                int row = g2 * 16 + (l & 7) + ((l >> 4) << 3);
                int col = ks * 16 + (((l >> 3) & 1) << 3);
                ldsm4(kh[g2], bK + (uint32_t)(row * 72 + col) * 2);
            }
#pragma unroll
            for (int f = 0; f < 8; f++)
                mma_f16(Sa[f], qh[ks], &kh[f >> 1][(f & 1) * 2]);
        }

        int c0 = (l & 3) << 1;
        float mx0 = -1e30f, mx1 = -1e30f;
#pragma unroll
        for (int f = 0; f < 8; f++) {
            int j = f * 8 + c0;
            float Ej0 = sE[j], Rj0 = sR[j], Ej1 = sE[j + 1], Rj1 = sR[j + 1];
            Sa[f][0] *= fminf(Ei0 * Rj0, Ej0 * Ri0);
            Sa[f][1] *= fminf(Ei0 * Rj1, Ej1 * Ri0);
            Sa[f][2] *= fminf(Ei1 * Rj0, Ej0 * Ri1);
            Sa[f][3] *= fminf(Ei1 * Rj1, Ej1 * Ri1);
            mx0 = fmaxf(mx0, fmaxf(Sa[f][0], Sa[f][1]));
            mx1 = fmaxf(mx1, fmaxf(Sa[f][2], Sa[f][3]));
        }
        mx0 = fmaxf(mx0, __shfl_xor_sync(0xffffffffu, mx0, 1));
        mx0 = fmaxf(mx0, __shfl_xor_sync(0xffffffffu, mx0, 2));
        mx1 = fmaxf(mx1, __shfl_xor_sync(0xffffffffu, mx1, 1));
        mx1 = fmaxf(mx1, __shfl_xor_sync(0xffffffffu, mx1, 2));

        float mn0 = fmaxf(m0v, mx0), mn1 = fmaxf(m1v, mx1);
        float sc0 = fast_exp(m0v - mn0), sc1 = fast_exp(m1v - mn1);
        m0v = mn0; m1v = mn1;
        l0v *= sc0; l1v *= sc1;
#pragma unroll
        for (int f = 0; f < 8; f++) {
            Oa[f][0] *= sc0; Oa[f][1] *= sc0;
            Oa[f][2] *= sc1; Oa[f][3] *= sc1;
        }

        uint32_t Ph[8][2];
        float rs0 = 0.f, rs1 = 0.f;
#pragma unroll
        for (int f = 0; f < 8; f++) {
            float p00 = fast_exp(Sa[f][0] - mn0);
            float p01 = fast_exp(Sa[f][1] - mn0);
            float p10 = fast_exp(Sa[f][2] - mn1);
            float p11 = fast_exp(Sa[f][3] - mn1);
            uint32_t h0 = pack2h(p00, p01);
            uint32_t h1 = pack2h(p10, p11);
            Ph[f][0] = h0; Ph[f][1] = h1;
            float2 f0 = __half22float2(*reinterpret_cast<__half2*>(&h0));
            float2 f1 = __half22float2(*reinterpret_cast<__half2*>(&h1));
            rs0 += f0.x + f0.y;
            rs1 += f1.x + f1.y;
        }
        rs0 += __shfl_xor_sync(0xffffffffu, rs0, 1);
        rs0 += __shfl_xor_sync(0xffffffffu, rs0, 2);
        rs1 += __shfl_xor_sync(0xffffffffu, rs1, 1);
        rs1 += __shfl_xor_sync(0xffffffffu, rs1, 2);
        l0v += rs0; l1v += rs1;

#pragma unroll
        for (int ks = 0; ks < 4; ks++) {
            uint32_t pah[4] = {Ph[2*ks][0], Ph[2*ks][1], Ph[2*ks+1][0], Ph[2*ks+1][1]};
            uint32_t vh[4][4], vl[4][4];
#pragma unroll
            for (int db = 0; db < 4; db++) {
                int row = ks * 16 + (l & 7) + (((l >> 3) & 1) << 3);
                int col = db * 16 + ((l >> 4) << 3);
                uint32_t off = (uint32_t)(row * 72 + col) * 2;
                ldsm4t(vh[db], bVh + off);
                ldsm4t(vl[db], bVl + off);
            }
#pragma unroll
            for (int db = 0; db < 4; db++) {
                mma_f16(Oa[2*db],   pah, &vh[db][0]);
                mma_f16(Oa[2*db+1], pah, &vh[db][2]);
            }
#pragma unroll
            for (int db = 0; db < 4; db++) {
                mma_f16(Oa[2*db],   pah, &vl[db][0]);
                mma_f16(Oa[2*db+1], pah, &vl[db][2]);
            }
        }
    }

    float inv0 = 1.0f / l0v, inv1 = 1.0f / l1v;
    int c0 = (l & 3) << 1;
    size_t ro0 = (size_t)(b * S_ + q0 + r0) * D_ + h * HD_;
    size_t ro1 = (size_t)(b * S_ + q0 + r1) * D_ + h * HD_;
#pragma unroll
    for (int f = 0; f < 8; f++) {
        int d = f * 8 + c0;
        float v00 = Oa[f][0] * inv0, v01 = Oa[f][1] * inv0;
        float v10 = Oa[f][2] * inv1, v11 = Oa[f][3] * inv1;
        __nv_bfloat162 h0, h1, lo0, lo1;
        h0.x = __float2bfloat16_rn(v00); h0.y = __float2bfloat16_rn(v01);
        h1.x = __float2bfloat16_rn(v10); h1.y = __float2bfloat16_rn(v11);
        lo0.x = __float2bfloat16_rn(v00 - __bfloat162float(h0.x));
        lo0.y = __float2bfloat16_rn(v01 - __bfloat162float(h0.y));
        lo1.x = __float2bfloat16_rn(v10 - __bfloat162float(h1.x));
        lo1.y = __float2bfloat16_rn(v11 - __bfloat162float(h1.y));
        *(__nv_bfloat162*)(g_aohi + ro0 + d) = h0;
        *(__nv_bfloat162*)(g_aohi + ro1 + d) = h1;
        *(__nv_bfloat162*)(g_aolo + ro0 + d) = lo0;
        *(__nv_bfloat162*)(g_aolo + ro1 + d) = lo1;
    }
}

// ---------------- launch ----------------
extern "C" void kernel_launch(void* const* d_in, const int* in_sizes, int n_in,
                              void* d_out, int out_size) {
    const float* x  = (const float*)d_in[0];
    const float* ts = (const float*)d_in[1];
    const float* Wq = (const float*)d_in[2];
    const float* bq = (const float*)d_in[3];
    const float* Wk = (const float*)d_in[4];
    const float* bk = (const float*)d_in[5];
    const float* Wv = (const float*)d_in[6];
    const float* bv = (const float*)d_in[7];
    const float* Wo = (const float*)d_in[8];
    const float* bo = (const float*)d_in[9];
    const float* td = (const float*)d_in[10];
    float* out = (float*)d_out;

    static int attr_done = 0;
    if (!attr_done) {
        cudaFuncSetAttribute(gemm_qkv, cudaFuncAttributeMaxDynamicSharedMemorySize, G2_SMEM);
        cudaFuncSetAttribute(gemm_o,   cudaFuncAttributeMaxDynamicSharedMemorySize, G_SMEM);
        cudaFuncSetAttribute(attn_mma, cudaFuncAttributeMaxDynamicSharedMemorySize, A_SMEM);
        attr_done = 1;
    }

    prep_kernel<<<M_ / 256, 256>>>(ts, td);
    xcvt_kernel<<<(M_ * D_) / 256, 256>>>(x);
    transpose_split_all<<<dim3(D_ / 32, D_ / 32, 4), dim3(32, 8)>>>(Wq, Wk, Wv, Wo);

    gemm_qkv<<<dim3(D_ / 128, M_ / 128, 3), 256, G2_SMEM>>>(bq, bk, bv);
    attn_mma<<<dim3(S_ / 64, H_, B_), 128, A_SMEM>>>();
    gemm_o<<<dim3(D_ / 128, M_ / 128), 256, G_SMEM>>>(bo, out);
}

// round 17
// speedup vs baseline: 1.5995x; 1.0909x over previous
#include <cuda_runtime.h>
#include <cuda_bf16.h>
#include <cuda_fp16.h>
#include <math.h>
#include <cstdint>

#define B_  2
#define S_  2048
#define D_  1024
#define H_  16
#define HD_ 64
#define M_  (B_*S_)

// ---------------- scratch (no allocs allowed) ----------------
__device__ float g_E[M_], g_R[M_];
__device__ __half        g_xf  [M_*D_];                       // x, fp16 single
__device__ __half        g_qf  [M_*D_];                       // q, fp16 single (1/8 folded)
__device__ __half        g_kf  [M_*D_];                       // k, fp16 single
__device__ __half        g_vf  [M_*D_];                       // v, fp16 single
__device__ __nv_bfloat16 g_aohi[M_*D_], g_aolo[M_*D_];
__device__ __half        g_wfh [3u*D_*D_], g_wfl [3u*D_*D_];  // Wq/Wk/Wv^T fp16 hi/lo
__device__ __nv_bfloat16 g_wthi[D_*D_],    g_wtlo[D_*D_];     // Wo^T bf16 hi/lo

// ================= helpers =================
__device__ __forceinline__ uint32_t smem_u32(const void* p) {
    uint32_t a;
    asm("{ .reg .u64 t; cvta.to.shared.u64 t, %1; cvt.u32.u64 %0, t; }" : "=r"(a) : "l"(p));
    return a;
}
__device__ __forceinline__ void ldsm4(uint32_t* r, uint32_t a) {
    asm volatile("ldmatrix.sync.aligned.m8n8.x4.shared.b16 {%0,%1,%2,%3}, [%4];"
        : "=r"(r[0]), "=r"(r[1]), "=r"(r[2]), "=r"(r[3]) : "r"(a));
}
__device__ __forceinline__ void ldsm4t(uint32_t* r, uint32_t a) {
    asm volatile("ldmatrix.sync.aligned.m8n8.x4.trans.shared.b16 {%0,%1,%2,%3}, [%4];"
        : "=r"(r[0]), "=r"(r[1]), "=r"(r[2]), "=r"(r[3]) : "r"(a));
}
__device__ __forceinline__ void mma_bf16(float* c, const uint32_t* a, const uint32_t* b) {
    asm volatile("mma.sync.aligned.m16n8k16.row.col.f32.bf16.bf16.f32 "
        "{%0,%1,%2,%3}, {%4,%5,%6,%7}, {%8,%9}, {%0,%1,%2,%3};"
        : "+f"(c[0]), "+f"(c[1]), "+f"(c[2]), "+f"(c[3])
        : "r"(a[0]), "r"(a[1]), "r"(a[2]), "r"(a[3]), "r"(b[0]), "r"(b[1]));
}
__device__ __forceinline__ void mma_f16(float* c, const uint32_t* a, const uint32_t* b) {
    asm volatile("mma.sync.aligned.m16n8k16.row.col.f32.f16.f16.f32 "
        "{%0,%1,%2,%3}, {%4,%5,%6,%7}, {%8,%9}, {%0,%1,%2,%3};"
        : "+f"(c[0]), "+f"(c[1]), "+f"(c[2]), "+f"(c[3])
        : "r"(a[0]), "r"(a[1]), "r"(a[2]), "r"(a[3]), "r"(b[0]), "r"(b[1]));
}
__device__ __forceinline__ uint32_t pack2h(float lo, float hi) {
    uint32_t r;
    asm("cvt.rn.f16x2.f32 %0, %1, %2;" : "=r"(r) : "f"(hi), "f"(lo));
    return r;
}

#define CP16(dst, src) asm volatile("cp.async.cg.shared.global [%0], [%1], 16;" :: "r"(dst), "l"(src))
#define CP_COMMIT()    asm volatile("cp.async.commit_group;" ::: "memory")
#define CP_WAIT0()     asm volatile("cp.async.wait_group 0;" ::: "memory")

// FFMA-only exp (x <= 0 expected)
__device__ __forceinline__ float fast_exp(float x) {
    x = fmaxf(x, -80.0f);
    float t = x * 1.4426950408889634f;
    float z = t + 12582912.0f;
    int  ni = __float_as_int(z) - 0x4B400000;
    float n = z - 12582912.0f;
    float g = fmaf(n, -0.6931471805599453f, x);
    float p = 1.3888889e-3f;
    p = fmaf(p, g, 8.3333333e-3f);
    p = fmaf(p, g, 4.1666667e-2f);
    p = fmaf(p, g, 1.6666667e-1f);
    p = fmaf(p, g, 0.5f);
    p = fmaf(p, g, 1.0f);
    p = fmaf(p, g, 1.0f);
    return p * __int_as_float((ni + 127) << 23);
}

// ---------------- small prep kernels ----------------
__global__ void prep_kernel(const float* __restrict__ ts, const float* __restrict__ td) {
    int i = blockIdx.x * 256 + threadIdx.x;
    if (i < M_) {
        float e = expf(td[0] * ts[i]);
        g_E[i] = e;
        g_R[i] = 1.0f / e;
    }
}
__global__ __launch_bounds__(256) void xcvt_kernel(const float* __restrict__ src) {
    int i = blockIdx.x * 256 + threadIdx.x;
    g_xf[i] = __float2half_rn(src[i]);
}
// transpose: z<3 -> fp16 hi/lo (Wq/Wk/Wv), z==3 -> bf16 hi/lo (Wo)
__global__ __launch_bounds__(256) void transpose_split_all(
    const float* __restrict__ W0, const float* __restrict__ W1,
    const float* __restrict__ W2, const float* __restrict__ W3)
{
    __shared__ float tile[32][33];
    int z = blockIdx.z;
    const float* W = (z == 0) ? W0 : (z == 1) ? W1 : (z == 2) ? W2 : W3;
    int tx = threadIdx.x, ty = threadIdx.y;
    int n0 = blockIdx.x * 32, k0 = blockIdx.y * 32;
#pragma unroll
    for (int j = 0; j < 32; j += 8)
        tile[ty + j][tx] = W[(size_t)(k0 + ty + j) * D_ + n0 + tx];
    __syncthreads();
    if (z < 3) {
        size_t zoff = (size_t)z * D_ * D_;
#pragma unroll
        for (int j = 0; j < 32; j += 8) {
            float f = tile[tx][ty + j];
            __half h = __float2half_rn(f);
            size_t o = zoff + (size_t)(n0 + ty + j) * D_ + k0 + tx;
            g_wfh[o] = h;
            g_wfl[o] = __float2half_rn(f - __half2float(h));
        }
    } else {
#pragma unroll
        for (int j = 0; j < 32; j += 8) {
            float f = tile[tx][ty + j];
            __nv_bfloat16 h = __float2bfloat16_rn(f);
            size_t o = (size_t)(n0 + ty + j) * D_ + k0 + tx;
            g_wthi[o] = h;
            g_wtlo[o] = __float2bfloat16_rn(f - __bfloat162float(h));
        }
    }
}

// ---------------- QKV: 2-stream fp16 GEMM (x single, W hi/lo), cp.async 2-stage ----------------
static constexpr int G2_STAGE = 30720;
static constexpr int G2_SMEM  = 2 * G2_STAGE;

__device__ __forceinline__ void qkv_issue_chunk(
    uint32_t sb, int stage, const __half* Bh, const __half* Bl,
    int m0, int n0, int k0, int tid)
{
    uint32_t st = sb + stage * G2_STAGE;
#pragma unroll
    for (int j = 0; j < 6; j++) {
        int a = j >> 1;
        int rem = tid + (j & 1) * 256;
        int r = rem >> 2, c4 = rem & 3;
        const __half* base = (a == 0) ? g_xf : (a == 1) ? Bh : Bl;
        int rowbase = (a == 0) ? m0 : n0;
        uint32_t dst = st + (uint32_t)a * 10240u + (uint32_t)(r * 80 + c4 * 16);
        const __half* src = base + (size_t)(rowbase + r) * D_ + k0 + c4 * 8;
        CP16(dst, src);
    }
    CP_COMMIT();
}

__global__ __launch_bounds__(256, 2) void gemm_qkv(
    const float* __restrict__ bq, const float* __restrict__ bk, const float* __restrict__ bv)
{
    extern __shared__ char smem[];
    uint32_t sb = smem_u32(smem);
    int z = blockIdx.z;
    const size_t WSZ = (size_t)D_ * D_;
    const __half* Bh = g_wfh + (size_t)z * WSZ;
    const __half* Bl = g_wfl + (size_t)z * WSZ;
    const float* bias = (z == 0) ? bq : (z == 1) ? bk : bv;
    __half* Hout = (z == 0) ? g_qf : (z == 1) ? g_kf : g_vf;
    float scale = (z == 0) ? 0.125f : 1.0f;

    int tid = threadIdx.x, l = tid & 31, wid = tid >> 5;
    int wm = wid >> 2, wn = wid & 3;
    int m0 = blockIdx.y * 128, n0 = blockIdx.x * 128;

    float acc[4][4][4];
#pragma unroll
    for (int a = 0; a < 4; a++)
#pragma unroll
        for (int b2 = 0; b2 < 4; b2++)
#pragma unroll
            for (int c = 0; c < 4; c++) acc[a][b2][c] = 0.f;

    qkv_issue_chunk(sb, 0, Bh, Bl, m0, n0, 0, tid);

    for (int kc = 0; kc < 32; kc++) {
        CP_WAIT0();
        __syncthreads();
        if (kc + 1 < 32)
            qkv_issue_chunk(sb, (kc + 1) & 1, Bh, Bl, m0, n0, (kc + 1) * 32, tid);

        uint32_t st = sb + (kc & 1) * G2_STAGE;
        uint32_t bA = st, bBh = st + 10240, bBl = st + 20480;
#pragma unroll
        for (int s = 0; s < 2; s++) {
            int k0 = s * 16;
            uint32_t af[4][4], bh[2][4], bl[2][4];
#pragma unroll
            for (int mi = 0; mi < 4; mi++) {
                int row = wm * 64 + mi * 16 + (l & 15);
                int col = k0 + ((l >> 4) << 3);
                ldsm4(af[mi], bA + (uint32_t)(row * 40 + col) * 2);
            }
#pragma unroll
            for (int np = 0; np < 2; np++) {
                int row = wn * 32 + np * 16 + (l & 7) + ((l >> 4) << 3);
                int col = k0 + (((l >> 3) & 1) << 3);
                uint32_t off = (uint32_t)(row * 40 + col) * 2;
                ldsm4(bh[np], bBh + off);
                ldsm4(bl[np], bBl + off);
            }
#pragma unroll
            for (int mi = 0; mi < 4; mi++)
#pragma unroll
                for (int ni = 0; ni < 4; ni++)
                    mma_f16(acc[mi][ni], af[mi], &bh[ni >> 1][(ni & 1) * 2]);
#pragma unroll
            for (int mi = 0; mi < 4; mi++)
#pragma unroll
                for (int ni = 0; ni < 4; ni++)
                    mma_f16(acc[mi][ni], af[mi], &bl[ni >> 1][(ni & 1) * 2]);
        }
    }
    // epilogue: fp16 single out
#pragma unroll
    for (int mi = 0; mi < 4; mi++) {
        int row0 = m0 + wm * 64 + mi * 16 + (l >> 2);
#pragma unroll
        for (int ni = 0; ni < 4; ni++) {
            int col = n0 + wn * 32 + ni * 8 + ((l & 3) << 1);
            float b0 = bias[col], b1 = bias[col + 1];
            float v00 = (acc[mi][ni][0] + b0) * scale;
            float v01 = (acc[mi][ni][1] + b1) * scale;
            float v10 = (acc[mi][ni][2] + b0) * scale;
            float v11 = (acc[mi][ni][3] + b1) * scale;
            size_t o0 = (size_t)row0 * D_ + col;
            size_t o1 = o0 + (size_t)8 * D_;
            __half2 h0, h1;
            h0.x = __float2half_rn(v00); h0.y = __float2half_rn(v01);
            h1.x = __float2half_rn(v10); h1.y = __float2half_rn(v11);
            *(__half2*)(Hout + o0) = h0;
            *(__half2*)(Hout + o1) = h1;
        }
    }
}

// ---------------- O-proj: 3-stream bf16 GEMM, cp.async 2-stage ----------------
static constexpr int G_STAGE = 40960;
static constexpr int G_SMEM  = 2 * G_STAGE;

__device__ __forceinline__ void o_issue_chunk(uint32_t sb, int stage, int m0, int n0, int k0, int tid) {
    uint32_t st = sb + stage * G_STAGE;
#pragma unroll
    for (int j = 0; j < 8; j++) {
        int rem = tid + (j & 1) * 256;
        int r = rem >> 2, c4 = rem & 3;
        const __nv_bfloat16* base = (j < 2) ? g_aohi : (j < 4) ? g_aolo : (j < 6) ? g_wthi : g_wtlo;
        int rowbase = (j < 4) ? m0 : n0;
        uint32_t dst = st + (uint32_t)(j >> 1) * 10240u + (uint32_t)(r * 80 + c4 * 16);
        const __nv_bfloat16* src = base + (size_t)(rowbase + r) * D_ + k0 + c4 * 8;
        CP16(dst, src);
    }
    CP_COMMIT();
}

__global__ __launch_bounds__(256, 2) void gemm_o(const float* __restrict__ bo, float* __restrict__ out)
{
    extern __shared__ char smem[];
    uint32_t sb = smem_u32(smem);
    int tid = threadIdx.x, l = tid & 31, wid = tid >> 5;
    int wm = wid >> 2, wn = wid & 3;
    int m0 = blockIdx.y * 128, n0 = blockIdx.x * 128;

    float acc[4][4][4];
#pragma unroll
    for (int a = 0; a < 4; a++)
#pragma unroll
        for (int b2 = 0; b2 < 4; b2++)
#pragma unroll
            for (int c = 0; c < 4; c++) acc[a][b2][c] = 0.f;

    o_issue_chunk(sb, 0, m0, n0, 0, tid);

    for (int kc = 0; kc < 32; kc++) {
        CP_WAIT0();
        __syncthreads();
        if (kc + 1 < 32)
            o_issue_chunk(sb, (kc + 1) & 1, m0, n0, (kc + 1) * 32, tid);

        uint32_t st  = sb + (kc & 1) * G_STAGE;
        uint32_t bAh = st, bAl = st + 10240, bBh = st + 20480, bBl = st + 30720;
#pragma unroll
        for (int s = 0; s < 2; s++) {
            int k0 = s * 16;
            uint32_t ah[4][4], al[4][4], bh[2][4], bl[2][4];
#pragma unroll
            for (int mi = 0; mi < 4; mi++) {
                int row = wm * 64 + mi * 16 + (l & 15);
                int col = k0 + ((l >> 4) << 3);
                uint32_t off = (uint32_t)(row * 40 + col) * 2;
                ldsm4(ah[mi], bAh + off);
                ldsm4(al[mi], bAl + off);
            }
#pragma unroll
            for (int np = 0; np < 2; np++) {
                int row = wn * 32 + np * 16 + (l & 7) + ((l >> 4) << 3);
                int col = k0 + (((l >> 3) & 1) << 3);
                uint32_t off = (uint32_t)(row * 40 + col) * 2;
                ldsm4(bh[np], bBh + off);
                ldsm4(bl[np], bBl + off);
            }
#pragma unroll
            for (int mi = 0; mi < 4; mi++)
#pragma unroll
                for (int ni = 0; ni < 4; ni++)
                    mma_bf16(acc[mi][ni], ah[mi], &bh[ni >> 1][(ni & 1) * 2]);
#pragma unroll
            for (int mi = 0; mi < 4; mi++)
#pragma unroll
                for (int ni = 0; ni < 4; ni++)
                    mma_bf16(acc[mi][ni], ah[mi], &bl[ni >> 1][(ni & 1) * 2]);
#pragma unroll
            for (int mi = 0; mi < 4; mi++)
#pragma unroll
                for (int ni = 0; ni < 4; ni++)
                    mma_bf16(acc[mi][ni], al[mi], &bh[ni >> 1][(ni & 1) * 2]);
        }
    }
#pragma unroll
    for (int mi = 0; mi < 4; mi++) {
        int row0 = m0 + wm * 64 + mi * 16 + (l >> 2);
#pragma unroll
        for (int ni = 0; ni < 4; ni++) {
            int col = n0 + wn * 32 + ni * 8 + ((l & 3) << 1);
            float b0 = bo[col], b1 = bo[col + 1];
            size_t o0 = (size_t)row0 * D_ + col;
            size_t o1 = o0 + (size_t)8 * D_;
            *(float2*)(out + o0) = make_float2(acc[mi][ni][0] + b0, acc[mi][ni][1] + b1);
            *(float2*)(out + o1) = make_float2(acc[mi][ni][2] + b0, acc[mi][ni][3] + b1);
        }
    }
}

// ---------------- fp16 HMMA flash attention (cp.async 2-stage, single-V) ----------------
// Stage (bytes): K 0..9216, V 9216..18432, E 18432, R 18688; stride 18944.
static constexpr int A_STAGE = 18944;
static constexpr int A_SMEM  = 2 * A_STAGE;

__device__ __forceinline__ void attn_issue_tile(uint32_t sb, int stage, int b, int h, int kt, int tid) {
    uint32_t st = sb + stage * A_STAGE;
#pragma unroll
    for (int j = 0; j < 8; j++) {
        int a = j >> 2;
        int rem = tid + (j & 3) * 128;
        int r = rem >> 3, c = rem & 7;
        const __half* base = (a == 0) ? g_kf : g_vf;
        uint32_t dst = st + (uint32_t)a * 9216u + (uint32_t)(r * 144 + c * 16);
        const __half* src = base + (size_t)(b * S_ + kt + r) * D_ + h * HD_ + c * 8;
        CP16(dst, src);
    }
    if (tid < 16)      CP16(st + 18432u + tid * 16, &g_E[b * S_ + kt + tid * 4]);
    else if (tid < 32) CP16(st + 18688u + (tid - 16) * 16, &g_R[b * S_ + kt + (tid - 16) * 4]);
    CP_COMMIT();
}

__global__ __launch_bounds__(128) void attn_mma() {
    extern __shared__ char smem[];
    uint32_t sb = smem_u32(smem);
    int tid = threadIdx.x, l = tid & 31, wid = tid >> 5;
    int h = blockIdx.y, b = blockIdx.z;
    int q0 = blockIdx.x * 64;

    __half* qstage = (__half*)smem;
    uint32_t qh[4][4];
#pragma unroll
    for (int t = 0; t < 4; t++) {
        int i = tid + t * 128;
        int r = i >> 3, c8 = (i & 7) << 3;
        *(uint4*)(qstage + r * 72 + c8) =
            *(const uint4*)(g_qf + (size_t)(b * S_ + q0 + r) * D_ + h * HD_ + c8);
    }
    __syncthreads();
#pragma unroll
    for (int ks = 0; ks < 4; ks++) {
        int row = wid * 16 + (l & 15);
        int col = ks * 16 + ((l >> 4) << 3);
        ldsm4(qh[ks], sb + (uint32_t)(row * 72 + col) * 2);
    }
    __syncthreads();

    int r0 = wid * 16 + (l >> 2), r1 = r0 + 8;
    float Ei0 = g_E[b * S_ + q0 + r0], Ri0 = g_R[b * S_ + q0 + r0];
    float Ei1 = g_E[b * S_ + q0 + r1], Ri1 = g_R[b * S_ + q0 + r1];

    float Oa[8][4];
#pragma unroll
    for (int f = 0; f < 8; f++)
#pragma unroll
        for (int c = 0; c < 4; c++) Oa[f][c] = 0.f;
    float m0v = -1e30f, m1v = -1e30f, l0v = 0.f, l1v = 0.f;

    attn_issue_tile(sb, 0, b, h, 0, tid);

    for (int t = 0; t < S_ / 64; t++) {
        CP_WAIT0();
        __syncthreads();
        if (t + 1 < S_ / 64)
            attn_issue_tile(sb, (t + 1) & 1, b, h, (t + 1) * 64, tid);

        uint32_t st = sb + (t & 1) * A_STAGE;
        uint32_t bK = st, bV = st + 9216;
        const float* sE = (const float*)(smem + (t & 1) * A_STAGE + 18432);
        const float* sR = (const float*)(smem + (t & 1) * A_STAGE + 18688);

        float Sa[8][4];
#pragma unroll
        for (int f = 0; f < 8; f++)
#pragma unroll
            for (int c = 0; c < 4; c++) Sa[f][c] = 0.f;
#pragma unroll
        for (int ks = 0; ks < 4; ks++) {
            uint32_t kh[4][4];
#pragma unroll
            for (int g2 = 0; g2 < 4; g2++) {
                int row = g2 * 16 + (l & 7) + ((l >> 4) << 3);
                int col = ks * 16 + (((l >> 3) & 1) << 3);
                ldsm4(kh[g2], bK + (uint32_t)(row * 72 + col) * 2);
            }
#pragma unroll
            for (int f = 0; f < 8; f++)
                mma_f16(Sa[f], qh[ks], &kh[f >> 1][(f & 1) * 2]);
        }

        int c0 = (l & 3) << 1;
        float mx0 = -1e30f, mx1 = -1e30f;
#pragma unroll
        for (int f = 0; f < 8; f++) {
            int j = f * 8 + c0;
            float Ej0 = sE[j], Rj0 = sR[j], Ej1 = sE[j + 1], Rj1 = sR[j + 1];
            Sa[f][0] *= fminf(Ei0 * Rj0, Ej0 * Ri0);
            Sa[f][1] *= fminf(Ei0 * Rj1, Ej1 * Ri0);
            Sa[f][2] *= fminf(Ei1 * Rj0, Ej0 * Ri1);
            Sa[f][3] *= fminf(Ei1 * Rj1, Ej1 * Ri1);
            mx0 = fmaxf(mx0, fmaxf(Sa[f][0], Sa[f][1]));
            mx1 = fmaxf(mx1, fmaxf(Sa[f][2], Sa[f][3]));
        }
        mx0 = fmaxf(mx0, __shfl_xor_sync(0xffffffffu, mx0, 1));
        mx0 = fmaxf(mx0, __shfl_xor_sync(0xffffffffu, mx0, 2));
        mx1 = fmaxf(mx1, __shfl_xor_sync(0xffffffffu, mx1, 1));
        mx1 = fmaxf(mx1, __shfl_xor_sync(0xffffffffu, mx1, 2));

        float mn0 = fmaxf(m0v, mx0), mn1 = fmaxf(m1v, mx1);
        float sc0 = fast_exp(m0v - mn0), sc1 = fast_exp(m1v - mn1);
        m0v = mn0; m1v = mn1;
        l0v *= sc0; l1v *= sc1;
#pragma unroll
        for (int f = 0; f < 8; f++) {
            Oa[f][0] *= sc0; Oa[f][1] *= sc0;
            Oa[f][2] *= sc1; Oa[f][3] *= sc1;
        }

        uint32_t Ph[8][2];
        float rs0 = 0.f, rs1 = 0.f;
#pragma unroll
        for (int f = 0; f < 8; f++) {
            float p00 = fast_exp(Sa[f][0] - mn0);
            float p01 = fast_exp(Sa[f][1] - mn0);
            float p10 = fast_exp(Sa[f][2] - mn1);
            float p11 = fast_exp(Sa[f][3] - mn1);
            uint32_t h0 = pack2h(p00, p01);
            uint32_t h1 = pack2h(p10, p11);
            Ph[f][0] = h0; Ph[f][1] = h1;
            float2 f0 = __half22float2(*reinterpret_cast<__half2*>(&h0));
            float2 f1 = __half22float2(*reinterpret_cast<__half2*>(&h1));
            rs0 += f0.x + f0.y;
            rs1 += f1.x + f1.y;
        }
        rs0 += __shfl_xor_sync(0xffffffffu, rs0, 1);
        rs0 += __shfl_xor_sync(0xffffffffu, rs0, 2);
        rs1 += __shfl_xor_sync(0xffffffffu, rs1, 1);
        rs1 += __shfl_xor_sync(0xffffffffu, rs1, 2);
        l0v += rs0; l1v += rs1;

        // O += P.V (single fp16 stream)
#pragma unroll
        for (int ks = 0; ks < 4; ks++) {
            uint32_t pah[4] = {Ph[2*ks][0], Ph[2*ks][1], Ph[2*ks+1][0], Ph[2*ks+1][1]};
            uint32_t vh[4][4];
#pragma unroll
            for (int db = 0; db < 4; db++) {
                int row = ks * 16 + (l & 7) + (((l >> 3) & 1) << 3);
                int col = db * 16 + ((l >> 4) << 3);
                ldsm4t(vh[db], bV + (uint32_t)(row * 72 + col) * 2);
            }
#pragma unroll
            for (int db = 0; db < 4; db++) {
                mma_f16(Oa[2*db],   pah, &vh[db][0]);
                mma_f16(Oa[2*db+1], pah, &vh[db][2]);
            }
        }
    }

    float inv0 = 1.0f / l0v, inv1 = 1.0f / l1v;
    int c0 = (l & 3) << 1;
    size_t ro0 = (size_t)(b * S_ + q0 + r0) * D_ + h * HD_;
    size_t ro1 = (size_t)(b * S_ + q0 + r1) * D_ + h * HD_;
#pragma unroll
    for (int f = 0; f < 8; f++) {
        int d = f * 8 + c0;
        float v00 = Oa[f][0] * inv0, v01 = Oa[f][1] * inv0;
        float v10 = Oa[f][2] * inv1, v11 = Oa[f][3] * inv1;
        __nv_bfloat162 h0, h1, lo0, lo1;
        h0.x = __float2bfloat16_rn(v00); h0.y = __float2bfloat16_rn(v01);
        h1.x = __float2bfloat16_rn(v10); h1.y = __float2bfloat16_rn(v11);
        lo0.x = __float2bfloat16_rn(v00 - __bfloat162float(h0.x));
        lo0.y = __float2bfloat16_rn(v01 - __bfloat162float(h0.y));
        lo1.x = __float2bfloat16_rn(v10 - __bfloat162float(h1.x));
        lo1.y = __float2bfloat16_rn(v11 - __bfloat162float(h1.y));
        *(__nv_bfloat162*)(g_aohi + ro0 + d) = h0;
        *(__nv_bfloat162*)(g_aohi + ro1 + d) = h1;
        *(__nv_bfloat162*)(g_aolo + ro0 + d) = lo0;
        *(__nv_bfloat162*)(g_aolo + ro1 + d) = lo1;
    }
}

// ---------------- launch ----------------
extern "C" void kernel_launch(void* const* d_in, const int* in_sizes, int n_in,
                              void* d_out, int out_size) {
    const float* x  = (const float*)d_in[0];
    const float* ts = (const float*)d_in[1];
    const float* Wq = (const float*)d_in[2];
    const float* bq = (const float*)d_in[3];
    const float* Wk = (const float*)d_in[4];
    const float* bk = (const float*)d_in[5];
    const float* Wv = (const float*)d_in[6];
    const float* bv = (const float*)d_in[7];
    const float* Wo = (const float*)d_in[8];
    const float* bo = (const float*)d_in[9];
    const float* td = (const float*)d_in[10];
    float* out = (float*)d_out;

    static int attr_done = 0;
    if (!attr_done) {
        cudaFuncSetAttribute(gemm_qkv, cudaFuncAttributeMaxDynamicSharedMemorySize, G2_SMEM);
        cudaFuncSetAttribute(gemm_o,   cudaFuncAttributeMaxDynamicSharedMemorySize, G_SMEM);
        cudaFuncSetAttribute(attn_mma, cudaFuncAttributeMaxDynamicSharedMemorySize, A_SMEM);
        attr_done = 1;
    }

    prep_kernel<<<M_ / 256, 256>>>(ts, td);
    xcvt_kernel<<<(M_ * D_) / 256, 256>>>(x);
    transpose_split_all<<<dim3(D_ / 32, D_ / 32, 4), dim3(32, 8)>>>(Wq, Wk, Wv, Wo);

    gemm_qkv<<<dim3(D_ / 128, M_ / 128, 3), 256, G2_SMEM>>>(bq, bk, bv);
    attn_mma<<<dim3(S_ / 64, H_, B_), 128, A_SMEM>>>();
    gemm_o<<<dim3(D_ / 128, M_ / 128), 256, G_SMEM>>>(bo, out);
}